// round 1
// baseline (speedup 1.0000x reference)
#include <cuda_runtime.h>

// Problem constants
#define HH 128
#define WW 48
#define HW 6144            // 128*48
#define KVLEN 5760         // 144*40
#define LOG2E_HALF 0.72134752044448170f   // 0.5 * log2(e)  (dph^-0.5 folded with exp->exp2)

// ---------------- scratch (device globals; zero-initialized at load) ----------------
__device__ float g_qs[32 * HW];          // q conv output, pre-scaled by 0.5*log2e
__device__ float g_kp[32 * 144 * 64];    // flange-padded k, layout [c=h*4+d][144][64]; pad stays 0
__device__ float g_vp[32 * 144 * 64];    // flange-padded v
__device__ float g_o [32 * HW];          // attention output (pre out-conv)
__device__ float g_wqkv[3 * 576 * 32];   // repacked [t][ci*9+ky*3+kx][co]
__device__ float g_wo[288 * 64];         // repacked [ci*9+ky*3+kx][co]

// ---------------- fast exp2 on the FMA pipe (no MUFU) ----------------
__device__ __forceinline__ float exp2p(float y) {
    // round-to-nearest integer via magic constant; |y| << 2^22 always holds here
    float r = y + 12582912.0f;                 // 1.5 * 2^23
    int   i = __float_as_int(r);
    float f = y - (r - 12582912.0f);           // f in [-0.5, 0.5]
    float p =              1.3333558146e-3f;
    p = fmaf(p, f, 9.6181291076e-3f);
    p = fmaf(p, f, 5.5504108664e-2f);
    p = fmaf(p, f, 2.4022650696e-1f);
    p = fmaf(p, f, 6.9314718056e-1f);
    p = fmaf(p, f, 1.0f);
    return __int_as_float(__float_as_int(p) + (i << 23));  // splice 2^n
}

// ---------------- weight repack: co-contiguous for broadcast LDS.128 ----------------
__global__ void repack_kernel(const float* __restrict__ wq, const float* __restrict__ wk,
                              const float* __restrict__ wv, const float* __restrict__ wo)
{
    int i = blockIdx.x * blockDim.x + threadIdx.x;
    if (i < 3 * 18432) {
        int t = i / 18432, r = i % 18432;
        int pos = r >> 5, co = r & 31;                 // pos = ci*9+ky*3+kx
        const float* w = (t == 0) ? wq : (t == 1) ? wk : wv;
        g_wqkv[i] = w[co * 576 + pos];
    } else if (i < 3 * 18432 + 18432) {
        int r = i - 3 * 18432;
        int pos = r >> 6, co = r & 63;
        g_wo[r] = wo[co * 288 + pos];
    }
}

// ---------------- QKV conv3x3 (CIN=64 -> 32), t = blockIdx.z selects q/k/v ----------
__global__ __launch_bounds__(128) void conv_qkv_kernel(
    const float* __restrict__ x,
    const float* __restrict__ bq, const float* __restrict__ bk, const float* __restrict__ bv)
{
    extern __shared__ float sm[];
    float* sx = sm;               // 64*10*18 = 11520 floats
    float* sw = sm + 11520;       // 576*32   = 18432 floats
    const int t  = blockIdx.z;
    const int y0 = blockIdx.y * 8, x0 = blockIdx.x * 16;
    const int tid = threadIdx.x;

    for (int idx = tid; idx < 11520; idx += 128) {
        int ci = idx / 180, rem = idx % 180;
        int ry = rem / 18, rx = rem % 18;
        int gy = y0 + ry - 1, gx = x0 + rx - 1;
        float v = 0.f;
        if (gy >= 0 && gy < HH && gx >= 0 && gx < WW) v = x[ci * HW + gy * WW + gx];
        sx[idx] = v;
    }
    {
        const float4* wsrc = (const float4*)(g_wqkv + t * 18432);
        float4* wdst = (float4*)sw;
        for (int idx = tid; idx < 4608; idx += 128) wdst[idx] = wsrc[idx];
    }
    __syncthreads();

    const int ty = tid >> 4, tx = tid & 15;
    const float* bias = (t == 0) ? bq : (t == 1) ? bk : bv;
    float acc[32];
    #pragma unroll
    for (int c = 0; c < 32; c++) acc[c] = bias[c];

    for (int ci = 0; ci < 64; ci++) {
        #pragma unroll
        for (int ky = 0; ky < 3; ky++) {
            #pragma unroll
            for (int kx = 0; kx < 3; kx++) {
                float xv = sx[(ci * 10 + ty + ky) * 18 + tx + kx];
                const float4* wr = (const float4*)&sw[(ci * 9 + ky * 3 + kx) * 32];
                #pragma unroll
                for (int jj = 0; jj < 8; jj++) {
                    float4 w4 = wr[jj];
                    acc[4*jj+0] = fmaf(xv, w4.x, acc[4*jj+0]);
                    acc[4*jj+1] = fmaf(xv, w4.y, acc[4*jj+1]);
                    acc[4*jj+2] = fmaf(xv, w4.z, acc[4*jj+2]);
                    acc[4*jj+3] = fmaf(xv, w4.w, acc[4*jj+3]);
                }
            }
        }
    }
    const int y = y0 + ty, xx = x0 + tx;
    if (t == 0) {
        #pragma unroll
        for (int c = 0; c < 32; c++)
            g_qs[c * HW + y * WW + xx] = acc[c] * LOG2E_HALF;
    } else {
        float* dst = (t == 1) ? g_kp : g_vp;
        #pragma unroll
        for (int c = 0; c < 32; c++)
            dst[(c * 144 + y + 8) * 64 + (xx + 8)] = acc[c];   // flange-padded interior
    }
}

// ---------------- block-local attention: grid (8 chunks, 16 blocks) -----------------
// blockIdx.y = n = h*2 + j ; each CTA: 192 threads x 2 queries = 384 queries.
__global__ __launch_bounds__(192) void attn_kernel()
{
    extern __shared__ float4 skv[];      // k4[5760] then v4[5760] : 184320 bytes
    float4* k4 = skv;
    float4* v4 = skv + KVLEN;

    const int n = blockIdx.y;
    const int h = n >> 1, j = n & 1;
    const int tid = threadIdx.x;

    // Gather flanged K/V via the exact as_strided flat-index map:
    // flat = h*24576 + d*6144 + m0*48 + j*24 + m1   (i=0, b=0)
    const int kbase = h * 24576 + j * 24;
    for (int m = tid; m < KVLEN; m += 192) {
        int m0 = m / 40, m1 = m - m0 * 40;
        int g = kbase + m0 * 48 + m1;
        k4[m] = make_float4(g_kp[g], g_kp[g + 6144], g_kp[g + 12288], g_kp[g + 18432]);
        v4[m] = make_float4(g_vp[g], g_vp[g + 6144], g_vp[g + 12288], g_vp[g + 18432]);
    }
    __syncthreads();

    const int qA = blockIdx.x * 384 + tid;
    const int qB = qA + 192;
    const int yA = qA / 24, xA = qA - yA * 24;
    const int yB = qB / 24, xB = qB - yB * 24;
    const int aA = yA * WW + j * 24 + xA;
    const int aB = yB * WW + j * 24 + xB;
    const int cb = h * 4 * HW;

    const float qa0 = g_qs[cb + aA],         qa1 = g_qs[cb + HW + aA];
    const float qa2 = g_qs[cb + 2*HW + aA],  qa3 = g_qs[cb + 3*HW + aA];
    const float qb0 = g_qs[cb + aB],         qb1 = g_qs[cb + HW + aB];
    const float qb2 = g_qs[cb + 2*HW + aB],  qb3 = g_qs[cb + 3*HW + aB];

    float aAx = 0.f, aAy = 0.f, aAz = 0.f, aAw = 0.f, denA = 0.f;
    float aBx = 0.f, aBy = 0.f, aBz = 0.f, aBw = 0.f, denB = 0.f;

    #pragma unroll 4
    for (int m = 0; m < KVLEN; m++) {
        float4 kk = k4[m];
        float4 vv = v4[m];
        float sA = fmaf(qa3, kk.w, fmaf(qa2, kk.z, fmaf(qa1, kk.y, qa0 * kk.x)));
        float sB = fmaf(qb3, kk.w, fmaf(qb2, kk.z, fmaf(qb1, kk.y, qb0 * kk.x)));
        float pA = exp2p(sA);
        float pB = exp2p(sB);
        denA += pA;
        denB += pB;
        aAx = fmaf(pA, vv.x, aAx); aAy = fmaf(pA, vv.y, aAy);
        aAz = fmaf(pA, vv.z, aAz); aAw = fmaf(pA, vv.w, aAw);
        aBx = fmaf(pB, vv.x, aBx); aBy = fmaf(pB, vv.y, aBy);
        aBz = fmaf(pB, vv.z, aBz); aBw = fmaf(pB, vv.w, aBw);
    }
    const float rA = 1.0f / denA;
    const float rB = 1.0f / denB;
    g_o[cb + aA]        = aAx * rA;
    g_o[cb + HW + aA]   = aAy * rA;
    g_o[cb + 2*HW + aA] = aAz * rA;
    g_o[cb + 3*HW + aA] = aAw * rA;
    g_o[cb + aB]        = aBx * rB;
    g_o[cb + HW + aB]   = aBy * rB;
    g_o[cb + 2*HW + aB] = aBz * rB;
    g_o[cb + 3*HW + aB] = aBw * rB;
}

// ---------------- output conv3x3 (CIN=32 -> 64), co halves by blockIdx.z ------------
__global__ __launch_bounds__(128) void conv_out_kernel(float* __restrict__ out)
{
    extern __shared__ float sm[];
    float* sx = sm;               // 32*10*18 = 5760 floats
    float* sw = sm + 5760;        // 288*32   = 9216 floats
    const int z  = blockIdx.z;
    const int y0 = blockIdx.y * 8, x0 = blockIdx.x * 16;
    const int tid = threadIdx.x;

    for (int idx = tid; idx < 5760; idx += 128) {
        int ci = idx / 180, rem = idx % 180;
        int ry = rem / 18, rx = rem % 18;
        int gy = y0 + ry - 1, gx = x0 + rx - 1;
        float v = 0.f;
        if (gy >= 0 && gy < HH && gx >= 0 && gx < WW) v = g_o[ci * HW + gy * WW + gx];
        sx[idx] = v;
    }
    for (int idx = tid; idx < 9216; idx += 128) {
        int pos = idx >> 5, c = idx & 31;
        sw[idx] = g_wo[pos * 64 + z * 32 + c];
    }
    __syncthreads();

    const int ty = tid >> 4, tx = tid & 15;
    float acc[32];
    #pragma unroll
    for (int c = 0; c < 32; c++) acc[c] = 0.f;

    for (int ci = 0; ci < 32; ci++) {
        #pragma unroll
        for (int ky = 0; ky < 3; ky++) {
            #pragma unroll
            for (int kx = 0; kx < 3; kx++) {
                float xv = sx[(ci * 10 + ty + ky) * 18 + tx + kx];
                const float4* wr = (const float4*)&sw[(ci * 9 + ky * 3 + kx) * 32];
                #pragma unroll
                for (int jj = 0; jj < 8; jj++) {
                    float4 w4 = wr[jj];
                    acc[4*jj+0] = fmaf(xv, w4.x, acc[4*jj+0]);
                    acc[4*jj+1] = fmaf(xv, w4.y, acc[4*jj+1]);
                    acc[4*jj+2] = fmaf(xv, w4.z, acc[4*jj+2]);
                    acc[4*jj+3] = fmaf(xv, w4.w, acc[4*jj+3]);
                }
            }
        }
    }
    const int y = y0 + ty, xx = x0 + tx;
    #pragma unroll
    for (int c = 0; c < 32; c++)
        out[(z * 32 + c) * HW + y * WW + xx] = acc[c];
}

// ---------------- launch ----------------
extern "C" void kernel_launch(void* const* d_in, const int* in_sizes, int n_in,
                              void* d_out, int out_size)
{
    const float* x  = (const float*)d_in[0];
    const float* wq = (const float*)d_in[1];
    const float* bq = (const float*)d_in[2];
    const float* wk = (const float*)d_in[3];
    const float* bk = (const float*)d_in[4];
    const float* wv = (const float*)d_in[5];
    const float* bv = (const float*)d_in[6];
    const float* wo = (const float*)d_in[7];
    float* out = (float*)d_out;

    // >48KB dynamic smem opt-ins (persist after first non-captured call)
    cudaFuncSetAttribute(conv_qkv_kernel, cudaFuncAttributeMaxDynamicSharedMemorySize, 119808);
    cudaFuncSetAttribute(attn_kernel,     cudaFuncAttributeMaxDynamicSharedMemorySize, 184320);
    cudaFuncSetAttribute(conv_out_kernel, cudaFuncAttributeMaxDynamicSharedMemorySize, 59904);

    repack_kernel<<<(73728 + 255) / 256, 256>>>(wq, wk, wv, wo);
    conv_qkv_kernel<<<dim3(3, 16, 3), 128, 119808>>>(x, bq, bk, bv);
    attn_kernel<<<dim3(8, 16), 192, 184320>>>();
    conv_out_kernel<<<dim3(3, 16, 2), 128, 59904>>>(out);
}

// round 2
// speedup vs baseline: 1.1333x; 1.1333x over previous
#include <cuda_runtime.h>

#define HH 128
#define WW 48
#define HW 6144            // 128*48
#define KVLEN 5760         // 144*40
#define LOG2E_HALF 0.72134752044448170f   // 0.5*log2(e): dph^-0.5 folded into exp->exp2

typedef unsigned long long ull;

// ---------------- scratch (device globals) ----------------
__device__ float g_qs[32 * HW];          // q conv output, pre-scaled
__device__ float g_kp[32 * 144 * 64];    // flange-padded k (flat, pad stays 0)
__device__ float g_vp[32 * 144 * 64];    // flange-padded v
__device__ float g_o [32 * HW];          // attention output
__device__ float g_wqkv[3 * 576 * 32];   // repacked [t][pos][co]
__device__ float g_wo[288 * 64];         // repacked [pos][co]

// ---------------- packed f32x2 helpers ----------------
__device__ __forceinline__ ull pk2(float a, float b) {
    ull r; asm("mov.b64 %0,{%1,%2};" : "=l"(r) : "f"(a), "f"(b)); return r;
}
__device__ __forceinline__ void upk2(float& a, float& b, ull v) {
    asm("mov.b64 {%0,%1},%2;" : "=f"(a), "=f"(b) : "l"(v));
}
__device__ __forceinline__ ull fma2(ull a, ull b, ull c) {
    ull d; asm("fma.rn.f32x2 %0,%1,%2,%3;" : "=l"(d) : "l"(a), "l"(b), "l"(c)); return d;
}
__device__ __forceinline__ ull add2(ull a, ull b) {
    ull d; asm("add.rn.f32x2 %0,%1,%2;" : "=l"(d) : "l"(a), "l"(b)); return d;
}
__device__ __forceinline__ ull mul2(ull a, ull b) {
    ull d; asm("mul.rn.f32x2 %0,%1,%2;" : "=l"(d) : "l"(a), "l"(b)); return d;
}

// ---------------- weight repack: co-contiguous ----------------
__global__ void repack_kernel(const float* __restrict__ wq, const float* __restrict__ wk,
                              const float* __restrict__ wv, const float* __restrict__ wo)
{
    int i = blockIdx.x * blockDim.x + threadIdx.x;
    if (i < 3 * 18432) {
        int t = i / 18432, r = i % 18432;
        int pos = r >> 5, co = r & 31;
        const float* w = (t == 0) ? wq : (t == 1) ? wk : wv;
        g_wqkv[i] = w[co * 576 + pos];
    } else if (i < 3 * 18432 + 18432) {
        int r = i - 3 * 18432;
        int pos = r >> 6, co = r & 63;
        g_wo[r] = wo[co * 288 + pos];
    }
}

// ---------------- QKV conv3x3 (64 -> 32), z = t*2 + co-half ----------------
__global__ __launch_bounds__(128) void conv_qkv_kernel(
    const float* __restrict__ x,
    const float* __restrict__ bq, const float* __restrict__ bk, const float* __restrict__ bv)
{
    extern __shared__ float sm[];
    float* sx = sm;               // 64*10*18 = 11520 floats
    float* sw = sm + 11520;       // 576*16   = 9216 floats
    const int t = blockIdx.z >> 1, half = blockIdx.z & 1;
    const int y0 = blockIdx.y * 8, x0 = blockIdx.x * 16;
    const int tid = threadIdx.x;

    for (int idx = tid; idx < 11520; idx += 128) {
        int ci = idx / 180, rem = idx % 180;
        int ry = rem / 18, rx = rem % 18;
        int gy = y0 + ry - 1, gx = x0 + rx - 1;
        float v = 0.f;
        if (gy >= 0 && gy < HH && gx >= 0 && gx < WW) v = x[ci * HW + gy * WW + gx];
        sx[idx] = v;
    }
    {
        const float* wsrc = g_wqkv + t * 18432 + half * 16;
        for (int idx = tid; idx < 2304; idx += 128) {
            int pos = idx >> 2, q = idx & 3;
            float4 w4 = *(const float4*)(wsrc + pos * 32 + q * 4);
            *(float4*)&sw[pos * 16 + q * 4] = w4;
        }
    }
    __syncthreads();

    const int ty = tid >> 4, tx = tid & 15;
    const float* bias = (t == 0) ? bq : (t == 1) ? bk : bv;
    float acc[16];
    #pragma unroll
    for (int c = 0; c < 16; c++) acc[c] = bias[half * 16 + c];

    for (int ci = 0; ci < 64; ci++) {
        #pragma unroll
        for (int ky = 0; ky < 3; ky++) {
            #pragma unroll
            for (int kx = 0; kx < 3; kx++) {
                float xv = sx[(ci * 10 + ty + ky) * 18 + tx + kx];
                const float4* wr = (const float4*)&sw[(ci * 9 + ky * 3 + kx) * 16];
                #pragma unroll
                for (int jj = 0; jj < 4; jj++) {
                    float4 w4 = wr[jj];
                    acc[4*jj+0] = fmaf(xv, w4.x, acc[4*jj+0]);
                    acc[4*jj+1] = fmaf(xv, w4.y, acc[4*jj+1]);
                    acc[4*jj+2] = fmaf(xv, w4.z, acc[4*jj+2]);
                    acc[4*jj+3] = fmaf(xv, w4.w, acc[4*jj+3]);
                }
            }
        }
    }
    const int y = y0 + ty, xx = x0 + tx;
    if (t == 0) {
        #pragma unroll
        for (int c = 0; c < 16; c++)
            g_qs[(half * 16 + c) * HW + y * WW + xx] = acc[c] * LOG2E_HALF;
    } else {
        float* dst = (t == 1) ? g_kp : g_vp;
        #pragma unroll
        for (int c = 0; c < 16; c++)
            dst[((half * 16 + c) * 144 + y + 8) * 64 + (xx + 8)] = acc[c];
    }
}

// ---------------- block-local attention: packed f32x2 over the m dimension ----------
// smem: component-sliced k/v: [comp][5760] each, k then v. 184320 bytes.
__global__ __launch_bounds__(192) void attn_kernel()
{
    extern __shared__ float sk[];
    // sk[c*5760 + m] = k comp c, sk[4*5760 + c*5760 + m] = v comp c
    const int n = blockIdx.y;
    const int h = n >> 1, j = n & 1;
    const int tid = threadIdx.x;

    // Stage flanged K/V (exact as_strided flat map), vectorized float4 over m1
    // flat = h*24576 + d*6144 + m0*48 + j*24 + m1
    {
        const int kbase = h * 24576 + j * 24;
        for (int it = tid; it < 2880; it += 192) {           // 2 comps-pairs worth: 4c*144r*10v/2
            int c = it / 720, rem = it % 720;                // handle 2 comps per it? no: split below
            (void)c; (void)rem;
            break;                                            // placeholder (replaced by loop below)
        }
        for (int it = tid; it < 5760; it += 192) {            // 4 comps * 144 rows * 10 vec4
            int c = it / 1440, rem = it % 1440;
            int row = rem / 10, v4 = rem % 10;
            int m = row * 40 + v4 * 4;
            int g = kbase + c * 6144 + row * 48 + v4 * 4;
            *(float4*)&sk[c * 5760 + m]            = *(const float4*)&g_kp[g];
            *(float4*)&sk[23040 + c * 5760 + m]    = *(const float4*)&g_vp[g];
        }
    }
    __syncthreads();

    const int qA = blockIdx.x * 384 + tid;
    const int qB = qA + 192;
    const int yA = qA / 24, xA = qA - yA * 24;
    const int yB = qB / 24, xB = qB - yB * 24;
    const int aA = yA * WW + j * 24 + xA;
    const int aB = yB * WW + j * 24 + xB;
    const int cb = h * 4 * HW;

    // packed query broadcasts (loop-invariant)
    const ull qa0 = pk2(g_qs[cb + aA],        g_qs[cb + aA]);
    const ull qa1 = pk2(g_qs[cb + HW + aA],   g_qs[cb + HW + aA]);
    const ull qa2 = pk2(g_qs[cb + 2*HW + aA], g_qs[cb + 2*HW + aA]);
    const ull qa3 = pk2(g_qs[cb + 3*HW + aA], g_qs[cb + 3*HW + aA]);
    const ull qb0 = pk2(g_qs[cb + aB],        g_qs[cb + aB]);
    const ull qb1 = pk2(g_qs[cb + HW + aB],   g_qs[cb + HW + aB]);
    const ull qb2 = pk2(g_qs[cb + 2*HW + aB], g_qs[cb + 2*HW + aB]);
    const ull qb3 = pk2(g_qs[cb + 3*HW + aB], g_qs[cb + 3*HW + aB]);

    // packed constants
    const ull MAG2 = pk2(12582912.0f, 12582912.0f);
    const ull NEG1 = pk2(-1.0f, -1.0f);
    const ull C5 = pk2(1.3333558146e-3f, 1.3333558146e-3f);
    const ull C4 = pk2(9.6181291076e-3f, 9.6181291076e-3f);
    const ull C3 = pk2(5.5504108664e-2f, 5.5504108664e-2f);
    const ull C2 = pk2(2.4022650696e-1f, 2.4022650696e-1f);
    const ull C1 = pk2(6.9314718056e-1f, 6.9314718056e-1f);
    const ull ONE2 = pk2(1.0f, 1.0f);

    ull denA = 0, aAx = 0, aAy = 0, aAz = 0, aAw = 0;
    ull denB = 0, aBx = 0, aBy = 0, aBz = 0, aBw = 0;

    auto qstep = [&](ull q0, ull q1, ull q2, ull q3,
                     ull kx, ull ky, ull kz, ull kw,
                     ull vx, ull vy, ull vz, ull vw,
                     ull& den, ull& ax, ull& ay, ull& az, ull& aw)
    {
        ull s2 = fma2(q3, kw, fma2(q2, kz, fma2(q1, ky, mul2(q0, kx))));
        ull r2 = add2(s2, MAG2);
        ull t2 = fma2(r2, NEG1, MAG2);        // C - r
        ull f2 = add2(s2, t2);                // s - (r - C)
        ull p2 = fma2(C5, f2, C4);
        p2 = fma2(p2, f2, C3);
        p2 = fma2(p2, f2, C2);
        p2 = fma2(p2, f2, C1);
        p2 = fma2(p2, f2, ONE2);
        // exponent splice per half (ALU pipe)
        float pl, ph, rl, rh;
        upk2(pl, ph, p2); upk2(rl, rh, r2);
        int el = __float_as_int(pl) + (__float_as_int(rl) << 23);
        int eh = __float_as_int(ph) + (__float_as_int(rh) << 23);
        ull e2 = pk2(__int_as_float(el), __int_as_float(eh));
        den = add2(den, e2);
        ax = fma2(e2, vx, ax); ay = fma2(e2, vy, ay);
        az = fma2(e2, vz, az); aw = fma2(e2, vw, aw);
    };

    const float* skx = sk;
    const float* sky = sk + 5760;
    const float* skz = sk + 11520;
    const float* skw = sk + 17280;
    const float* svx = sk + 23040;
    const float* svy = sk + 28800;
    const float* svz = sk + 34560;
    const float* svw = sk + 40320;

    for (int m = 0; m < KVLEN; m += 4) {
        ulonglong2 kx = *(const ulonglong2*)(skx + m);
        ulonglong2 ky = *(const ulonglong2*)(sky + m);
        ulonglong2 kz = *(const ulonglong2*)(skz + m);
        ulonglong2 kw = *(const ulonglong2*)(skw + m);
        ulonglong2 vx = *(const ulonglong2*)(svx + m);
        ulonglong2 vy = *(const ulonglong2*)(svy + m);
        ulonglong2 vz = *(const ulonglong2*)(svz + m);
        ulonglong2 vw = *(const ulonglong2*)(svw + m);
        qstep(qa0,qa1,qa2,qa3, kx.x,ky.x,kz.x,kw.x, vx.x,vy.x,vz.x,vw.x, denA,aAx,aAy,aAz,aAw);
        qstep(qa0,qa1,qa2,qa3, kx.y,ky.y,kz.y,kw.y, vx.y,vy.y,vz.y,vw.y, denA,aAx,aAy,aAz,aAw);
        qstep(qb0,qb1,qb2,qb3, kx.x,ky.x,kz.x,kw.x, vx.x,vy.x,vz.x,vw.x, denB,aBx,aBy,aBz,aBw);
        qstep(qb0,qb1,qb2,qb3, kx.y,ky.y,kz.y,kw.y, vx.y,vy.y,vz.y,vw.y, denB,aBx,aBy,aBz,aBw);
    }

    float lo, hi, d0, d1;
    upk2(d0, d1, denA); const float rA = 1.0f / (d0 + d1);
    upk2(d0, d1, denB); const float rB = 1.0f / (d0 + d1);
    upk2(lo, hi, aAx); g_o[cb + aA]        = (lo + hi) * rA;
    upk2(lo, hi, aAy); g_o[cb + HW + aA]   = (lo + hi) * rA;
    upk2(lo, hi, aAz); g_o[cb + 2*HW + aA] = (lo + hi) * rA;
    upk2(lo, hi, aAw); g_o[cb + 3*HW + aA] = (lo + hi) * rA;
    upk2(lo, hi, aBx); g_o[cb + aB]        = (lo + hi) * rB;
    upk2(lo, hi, aBy); g_o[cb + HW + aB]   = (lo + hi) * rB;
    upk2(lo, hi, aBz); g_o[cb + 2*HW + aB] = (lo + hi) * rB;
    upk2(lo, hi, aBw); g_o[cb + 3*HW + aB] = (lo + hi) * rB;
}

// ---------------- output conv3x3 (32 -> 64), z = co quarter ----------------
__global__ __launch_bounds__(128) void conv_out_kernel(float* __restrict__ out)
{
    extern __shared__ float sm[];
    float* sx = sm;               // 32*10*18 = 5760 floats
    float* sw = sm + 5760;        // 288*16   = 4608 floats
    const int z  = blockIdx.z;
    const int y0 = blockIdx.y * 8, x0 = blockIdx.x * 16;
    const int tid = threadIdx.x;

    for (int idx = tid; idx < 5760; idx += 128) {
        int ci = idx / 180, rem = idx % 180;
        int ry = rem / 18, rx = rem % 18;
        int gy = y0 + ry - 1, gx = x0 + rx - 1;
        float v = 0.f;
        if (gy >= 0 && gy < HH && gx >= 0 && gx < WW) v = g_o[ci * HW + gy * WW + gx];
        sx[idx] = v;
    }
    for (int idx = tid; idx < 1152; idx += 128) {
        int pos = idx >> 2, q = idx & 3;
        float4 w4 = *(const float4*)(g_wo + pos * 64 + z * 16 + q * 4);
        *(float4*)&sw[pos * 16 + q * 4] = w4;
    }
    __syncthreads();

    const int ty = tid >> 4, tx = tid & 15;
    float acc[16];
    #pragma unroll
    for (int c = 0; c < 16; c++) acc[c] = 0.f;

    for (int ci = 0; ci < 32; ci++) {
        #pragma unroll
        for (int ky = 0; ky < 3; ky++) {
            #pragma unroll
            for (int kx = 0; kx < 3; kx++) {
                float xv = sx[(ci * 10 + ty + ky) * 18 + tx + kx];
                const float4* wr = (const float4*)&sw[(ci * 9 + ky * 3 + kx) * 16];
                #pragma unroll
                for (int jj = 0; jj < 4; jj++) {
                    float4 w4 = wr[jj];
                    acc[4*jj+0] = fmaf(xv, w4.x, acc[4*jj+0]);
                    acc[4*jj+1] = fmaf(xv, w4.y, acc[4*jj+1]);
                    acc[4*jj+2] = fmaf(xv, w4.z, acc[4*jj+2]);
                    acc[4*jj+3] = fmaf(xv, w4.w, acc[4*jj+3]);
                }
            }
        }
    }
    const int y = y0 + ty, xx = x0 + tx;
    #pragma unroll
    for (int c = 0; c < 16; c++)
        out[(z * 16 + c) * HW + y * WW + xx] = acc[c];
}

// ---------------- launch ----------------
extern "C" void kernel_launch(void* const* d_in, const int* in_sizes, int n_in,
                              void* d_out, int out_size)
{
    const float* x  = (const float*)d_in[0];
    const float* wq = (const float*)d_in[1];
    const float* bq = (const float*)d_in[2];
    const float* wk = (const float*)d_in[3];
    const float* bk = (const float*)d_in[4];
    const float* wv = (const float*)d_in[5];
    const float* bv = (const float*)d_in[6];
    const float* wo = (const float*)d_in[7];
    float* out = (float*)d_out;

    cudaFuncSetAttribute(conv_qkv_kernel, cudaFuncAttributeMaxDynamicSharedMemorySize, 82944);
    cudaFuncSetAttribute(attn_kernel,     cudaFuncAttributeMaxDynamicSharedMemorySize, 184320);
    cudaFuncSetAttribute(conv_out_kernel, cudaFuncAttributeMaxDynamicSharedMemorySize, 41472);

    repack_kernel<<<(73728 + 255) / 256, 256>>>(wq, wk, wv, wo);
    conv_qkv_kernel<<<dim3(3, 16, 6), 128, 82944>>>(x, bq, bk, bv);
    attn_kernel<<<dim3(8, 16), 192, 184320>>>();
    conv_out_kernel<<<dim3(3, 16, 4), 128, 41472>>>(out);
}

// round 3
// speedup vs baseline: 1.1348x; 1.0013x over previous
#include <cuda_runtime.h>

#define HH 128
#define WW 48
#define HW 6144            // 128*48
#define KVLEN 5760         // 144*40
#define LOG2E_HALF 0.72134752044448170f   // 0.5*log2(e): dph^-0.5 folded into exp->exp2

typedef unsigned long long ull;

// ---------------- scratch (device globals) ----------------
__device__ float g_qs[32 * HW];          // q conv output, pre-scaled
__device__ float g_kp[32 * 144 * 64];    // flange-padded k (flat, pad stays 0)
__device__ float g_vp[32 * 144 * 64];    // flange-padded v
__device__ float g_o [32 * HW];          // attention output
__device__ float g_wqkv[3 * 576 * 32];   // repacked [t][pos][co]
__device__ float g_wo[288 * 64];         // repacked [pos][co]

// ---------------- packed f32x2 helpers ----------------
__device__ __forceinline__ ull pk2(float a, float b) {
    ull r; asm("mov.b64 %0,{%1,%2};" : "=l"(r) : "f"(a), "f"(b)); return r;
}
__device__ __forceinline__ void upk2(float& a, float& b, ull v) {
    asm("mov.b64 {%0,%1},%2;" : "=f"(a), "=f"(b) : "l"(v));
}
__device__ __forceinline__ ull fma2(ull a, ull b, ull c) {
    ull d; asm("fma.rn.f32x2 %0,%1,%2,%3;" : "=l"(d) : "l"(a), "l"(b), "l"(c)); return d;
}
__device__ __forceinline__ ull add2(ull a, ull b) {
    ull d; asm("add.rn.f32x2 %0,%1,%2;" : "=l"(d) : "l"(a), "l"(b)); return d;
}
__device__ __forceinline__ ull mul2(ull a, ull b) {
    ull d; asm("mul.rn.f32x2 %0,%1,%2;" : "=l"(d) : "l"(a), "l"(b)); return d;
}

// ---------------- weight repack: co-contiguous ----------------
__global__ void repack_kernel(const float* __restrict__ wq, const float* __restrict__ wk,
                              const float* __restrict__ wv, const float* __restrict__ wo)
{
    int i = blockIdx.x * blockDim.x + threadIdx.x;
    if (i < 3 * 18432) {
        int t = i / 18432, r = i % 18432;
        int pos = r >> 5, co = r & 31;
        const float* w = (t == 0) ? wq : (t == 1) ? wk : wv;
        g_wqkv[i] = w[co * 576 + pos];
    } else if (i < 3 * 18432 + 18432) {
        int r = i - 3 * 18432;
        int pos = r >> 6, co = r & 63;
        g_wo[r] = wo[co * 288 + pos];
    }
}

// ---------------- QKV conv3x3 (64 -> 32), z = t*2 + co-half ----------------
__global__ __launch_bounds__(128) void conv_qkv_kernel(
    const float* __restrict__ x,
    const float* __restrict__ bq, const float* __restrict__ bk, const float* __restrict__ bv)
{
    extern __shared__ float sm[];
    float* sx = sm;               // 64*10*18 = 11520 floats
    float* sw = sm + 11520;       // 576*16   = 9216 floats
    const int t = blockIdx.z >> 1, half = blockIdx.z & 1;
    const int y0 = blockIdx.y * 8, x0 = blockIdx.x * 16;
    const int tid = threadIdx.x;

    for (int idx = tid; idx < 11520; idx += 128) {
        int ci = idx / 180, rem = idx % 180;
        int ry = rem / 18, rx = rem % 18;
        int gy = y0 + ry - 1, gx = x0 + rx - 1;
        float v = 0.f;
        if (gy >= 0 && gy < HH && gx >= 0 && gx < WW) v = x[ci * HW + gy * WW + gx];
        sx[idx] = v;
    }
    {
        const float* wsrc = g_wqkv + t * 18432 + half * 16;
        for (int idx = tid; idx < 2304; idx += 128) {
            int pos = idx >> 2, q = idx & 3;
            float4 w4 = *(const float4*)(wsrc + pos * 32 + q * 4);
            *(float4*)&sw[pos * 16 + q * 4] = w4;
        }
    }
    __syncthreads();

    const int ty = tid >> 4, tx = tid & 15;
    const float* bias = (t == 0) ? bq : (t == 1) ? bk : bv;
    float acc[16];
    #pragma unroll
    for (int c = 0; c < 16; c++) acc[c] = bias[half * 16 + c];

    for (int ci = 0; ci < 64; ci++) {
        #pragma unroll
        for (int ky = 0; ky < 3; ky++) {
            #pragma unroll
            for (int kx = 0; kx < 3; kx++) {
                float xv = sx[(ci * 10 + ty + ky) * 18 + tx + kx];
                const float4* wr = (const float4*)&sw[(ci * 9 + ky * 3 + kx) * 16];
                #pragma unroll
                for (int jj = 0; jj < 4; jj++) {
                    float4 w4 = wr[jj];
                    acc[4*jj+0] = fmaf(xv, w4.x, acc[4*jj+0]);
                    acc[4*jj+1] = fmaf(xv, w4.y, acc[4*jj+1]);
                    acc[4*jj+2] = fmaf(xv, w4.z, acc[4*jj+2]);
                    acc[4*jj+3] = fmaf(xv, w4.w, acc[4*jj+3]);
                }
            }
        }
    }
    const int y = y0 + ty, xx = x0 + tx;
    if (t == 0) {
        #pragma unroll
        for (int c = 0; c < 16; c++)
            g_qs[(half * 16 + c) * HW + y * WW + xx] = acc[c] * LOG2E_HALF;
    } else {
        float* dst = (t == 1) ? g_kp : g_vp;
        #pragma unroll
        for (int c = 0; c < 16; c++)
            dst[((half * 16 + c) * 144 + y + 8) * 64 + (xx + 8)] = acc[c];
    }
}

// ---------------- block-local attention: packed f32x2 over the m dimension ----------
// smem: component-sliced k/v: [comp][5760] each, k then v. 184320 bytes.
__global__ __launch_bounds__(192) void attn_kernel()
{
    extern __shared__ float sk[];
    // sk[c*5760 + m] = k comp c, sk[4*5760 + c*5760 + m] = v comp c
    const int n = blockIdx.y;
    const int h = n >> 1, j = n & 1;
    const int tid = threadIdx.x;

    // Stage flanged K/V (exact as_strided flat map), vectorized float4 over m1
    // flat = h*24576 + d*6144 + m0*48 + j*24 + m1
    {
        const int kbase = h * 24576 + j * 24;
        for (int it = tid; it < 2880; it += 192) {           // 2 comps-pairs worth: 4c*144r*10v/2
            int c = it / 720, rem = it % 720;                // handle 2 comps per it? no: split below
            (void)c; (void)rem;
            break;                                            // placeholder (replaced by loop below)
        }
        for (int it = tid; it < 5760; it += 192) {            // 4 comps * 144 rows * 10 vec4
            int c = it / 1440, rem = it % 1440;
            int row = rem / 10, v4 = rem % 10;
            int m = row * 40 + v4 * 4;
            int g = kbase + c * 6144 + row * 48 + v4 * 4;
            *(float4*)&sk[c * 5760 + m]            = *(const float4*)&g_kp[g];
            *(float4*)&sk[23040 + c * 5760 + m]    = *(const float4*)&g_vp[g];
        }
    }
    __syncthreads();

    const int qA = blockIdx.x * 384 + tid;
    const int qB = qA + 192;
    const int yA = qA / 24, xA = qA - yA * 24;
    const int yB = qB / 24, xB = qB - yB * 24;
    const int aA = yA * WW + j * 24 + xA;
    const int aB = yB * WW + j * 24 + xB;
    const int cb = h * 4 * HW;

    // packed query broadcasts (loop-invariant)
    const ull qa0 = pk2(g_qs[cb + aA],        g_qs[cb + aA]);
    const ull qa1 = pk2(g_qs[cb + HW + aA],   g_qs[cb + HW + aA]);
    const ull qa2 = pk2(g_qs[cb + 2*HW + aA], g_qs[cb + 2*HW + aA]);
    const ull qa3 = pk2(g_qs[cb + 3*HW + aA], g_qs[cb + 3*HW + aA]);
    const ull qb0 = pk2(g_qs[cb + aB],        g_qs[cb + aB]);
    const ull qb1 = pk2(g_qs[cb + HW + aB],   g_qs[cb + HW + aB]);
    const ull qb2 = pk2(g_qs[cb + 2*HW + aB], g_qs[cb + 2*HW + aB]);
    const ull qb3 = pk2(g_qs[cb + 3*HW + aB], g_qs[cb + 3*HW + aB]);

    // packed constants
    const ull MAG2 = pk2(12582912.0f, 12582912.0f);
    const ull NEG1 = pk2(-1.0f, -1.0f);
    const ull C5 = pk2(1.3333558146e-3f, 1.3333558146e-3f);
    const ull C4 = pk2(9.6181291076e-3f, 9.6181291076e-3f);
    const ull C3 = pk2(5.5504108664e-2f, 5.5504108664e-2f);
    const ull C2 = pk2(2.4022650696e-1f, 2.4022650696e-1f);
    const ull C1 = pk2(6.9314718056e-1f, 6.9314718056e-1f);
    const ull ONE2 = pk2(1.0f, 1.0f);

    ull denA = 0, aAx = 0, aAy = 0, aAz = 0, aAw = 0;
    ull denB = 0, aBx = 0, aBy = 0, aBz = 0, aBw = 0;

    auto qstep = [&](ull q0, ull q1, ull q2, ull q3,
                     ull kx, ull ky, ull kz, ull kw,
                     ull vx, ull vy, ull vz, ull vw,
                     ull& den, ull& ax, ull& ay, ull& az, ull& aw)
    {
        ull s2 = fma2(q3, kw, fma2(q2, kz, fma2(q1, ky, mul2(q0, kx))));
        ull r2 = add2(s2, MAG2);
        ull t2 = fma2(r2, NEG1, MAG2);        // C - r
        ull f2 = add2(s2, t2);                // s - (r - C)
        ull p2 = fma2(C5, f2, C4);
        p2 = fma2(p2, f2, C3);
        p2 = fma2(p2, f2, C2);
        p2 = fma2(p2, f2, C1);
        p2 = fma2(p2, f2, ONE2);
        // exponent splice per half (ALU pipe)
        float pl, ph, rl, rh;
        upk2(pl, ph, p2); upk2(rl, rh, r2);
        int el = __float_as_int(pl) + (__float_as_int(rl) << 23);
        int eh = __float_as_int(ph) + (__float_as_int(rh) << 23);
        ull e2 = pk2(__int_as_float(el), __int_as_float(eh));
        den = add2(den, e2);
        ax = fma2(e2, vx, ax); ay = fma2(e2, vy, ay);
        az = fma2(e2, vz, az); aw = fma2(e2, vw, aw);
    };

    const float* skx = sk;
    const float* sky = sk + 5760;
    const float* skz = sk + 11520;
    const float* skw = sk + 17280;
    const float* svx = sk + 23040;
    const float* svy = sk + 28800;
    const float* svz = sk + 34560;
    const float* svw = sk + 40320;

    for (int m = 0; m < KVLEN; m += 4) {
        ulonglong2 kx = *(const ulonglong2*)(skx + m);
        ulonglong2 ky = *(const ulonglong2*)(sky + m);
        ulonglong2 kz = *(const ulonglong2*)(skz + m);
        ulonglong2 kw = *(const ulonglong2*)(skw + m);
        ulonglong2 vx = *(const ulonglong2*)(svx + m);
        ulonglong2 vy = *(const ulonglong2*)(svy + m);
        ulonglong2 vz = *(const ulonglong2*)(svz + m);
        ulonglong2 vw = *(const ulonglong2*)(svw + m);
        qstep(qa0,qa1,qa2,qa3, kx.x,ky.x,kz.x,kw.x, vx.x,vy.x,vz.x,vw.x, denA,aAx,aAy,aAz,aAw);
        qstep(qa0,qa1,qa2,qa3, kx.y,ky.y,kz.y,kw.y, vx.y,vy.y,vz.y,vw.y, denA,aAx,aAy,aAz,aAw);
        qstep(qb0,qb1,qb2,qb3, kx.x,ky.x,kz.x,kw.x, vx.x,vy.x,vz.x,vw.x, denB,aBx,aBy,aBz,aBw);
        qstep(qb0,qb1,qb2,qb3, kx.y,ky.y,kz.y,kw.y, vx.y,vy.y,vz.y,vw.y, denB,aBx,aBy,aBz,aBw);
    }

    float lo, hi, d0, d1;
    upk2(d0, d1, denA); const float rA = 1.0f / (d0 + d1);
    upk2(d0, d1, denB); const float rB = 1.0f / (d0 + d1);
    upk2(lo, hi, aAx); g_o[cb + aA]        = (lo + hi) * rA;
    upk2(lo, hi, aAy); g_o[cb + HW + aA]   = (lo + hi) * rA;
    upk2(lo, hi, aAz); g_o[cb + 2*HW + aA] = (lo + hi) * rA;
    upk2(lo, hi, aAw); g_o[cb + 3*HW + aA] = (lo + hi) * rA;
    upk2(lo, hi, aBx); g_o[cb + aB]        = (lo + hi) * rB;
    upk2(lo, hi, aBy); g_o[cb + HW + aB]   = (lo + hi) * rB;
    upk2(lo, hi, aBz); g_o[cb + 2*HW + aB] = (lo + hi) * rB;
    upk2(lo, hi, aBw); g_o[cb + 3*HW + aB] = (lo + hi) * rB;
}

// ---------------- output conv3x3 (32 -> 64), z = co quarter ----------------
__global__ __launch_bounds__(128) void conv_out_kernel(float* __restrict__ out)
{
    extern __shared__ float sm[];
    float* sx = sm;               // 32*10*18 = 5760 floats
    float* sw = sm + 5760;        // 288*16   = 4608 floats
    const int z  = blockIdx.z;
    const int y0 = blockIdx.y * 8, x0 = blockIdx.x * 16;
    const int tid = threadIdx.x;

    for (int idx = tid; idx < 5760; idx += 128) {
        int ci = idx / 180, rem = idx % 180;
        int ry = rem / 18, rx = rem % 18;
        int gy = y0 + ry - 1, gx = x0 + rx - 1;
        float v = 0.f;
        if (gy >= 0 && gy < HH && gx >= 0 && gx < WW) v = g_o[ci * HW + gy * WW + gx];
        sx[idx] = v;
    }
    for (int idx = tid; idx < 1152; idx += 128) {
        int pos = idx >> 2, q = idx & 3;
        float4 w4 = *(const float4*)(g_wo + pos * 64 + z * 16 + q * 4);
        *(float4*)&sw[pos * 16 + q * 4] = w4;
    }
    __syncthreads();

    const int ty = tid >> 4, tx = tid & 15;
    float acc[16];
    #pragma unroll
    for (int c = 0; c < 16; c++) acc[c] = 0.f;

    for (int ci = 0; ci < 32; ci++) {
        #pragma unroll
        for (int ky = 0; ky < 3; ky++) {
            #pragma unroll
            for (int kx = 0; kx < 3; kx++) {
                float xv = sx[(ci * 10 + ty + ky) * 18 + tx + kx];
                const float4* wr = (const float4*)&sw[(ci * 9 + ky * 3 + kx) * 16];
                #pragma unroll
                for (int jj = 0; jj < 4; jj++) {
                    float4 w4 = wr[jj];
                    acc[4*jj+0] = fmaf(xv, w4.x, acc[4*jj+0]);
                    acc[4*jj+1] = fmaf(xv, w4.y, acc[4*jj+1]);
                    acc[4*jj+2] = fmaf(xv, w4.z, acc[4*jj+2]);
                    acc[4*jj+3] = fmaf(xv, w4.w, acc[4*jj+3]);
                }
            }
        }
    }
    const int y = y0 + ty, xx = x0 + tx;
    #pragma unroll
    for (int c = 0; c < 16; c++)
        out[(z * 16 + c) * HW + y * WW + xx] = acc[c];
}

// ---------------- launch ----------------
extern "C" void kernel_launch(void* const* d_in, const int* in_sizes, int n_in,
                              void* d_out, int out_size)
{
    const float* x  = (const float*)d_in[0];
    const float* wq = (const float*)d_in[1];
    const float* bq = (const float*)d_in[2];
    const float* wk = (const float*)d_in[3];
    const float* bk = (const float*)d_in[4];
    const float* wv = (const float*)d_in[5];
    const float* bv = (const float*)d_in[6];
    const float* wo = (const float*)d_in[7];
    float* out = (float*)d_out;

    cudaFuncSetAttribute(conv_qkv_kernel, cudaFuncAttributeMaxDynamicSharedMemorySize, 82944);
    cudaFuncSetAttribute(attn_kernel,     cudaFuncAttributeMaxDynamicSharedMemorySize, 184320);
    cudaFuncSetAttribute(conv_out_kernel, cudaFuncAttributeMaxDynamicSharedMemorySize, 41472);

    repack_kernel<<<(73728 + 255) / 256, 256>>>(wq, wk, wv, wo);
    conv_qkv_kernel<<<dim3(3, 16, 6), 128, 82944>>>(x, bq, bk, bv);
    attn_kernel<<<dim3(8, 16), 192, 184320>>>();
    conv_out_kernel<<<dim3(3, 16, 4), 128, 41472>>>(out);
}

// round 4
// speedup vs baseline: 1.3871x; 1.2224x over previous
#include <cuda_runtime.h>

#define HH 128
#define WW 48
#define HW 6144            // 128*48
#define MLEN 2880          // half of KVLEN=5760 (split-KV)
#define LOG2E_HALF 0.72134752044448170f   // 0.5*log2(e)

typedef unsigned long long ull;

// ---------------- scratch (device globals) ----------------
__device__ float g_qs[32 * HW];          // q conv output, pre-scaled
__device__ float g_kp[32 * 144 * 64];    // flange-padded k (flat, pad stays 0)
__device__ float g_vp[32 * 144 * 64];    // flange-padded v
__device__ float g_o [32 * HW];          // attention output
__device__ float g_wqkv[3 * 576 * 32];   // repacked [t][pos][co]
__device__ float g_wo[288 * 64];         // repacked [pos][co]
__device__ float g_pnum[2 * 16 * 4 * 3072];  // partial numerators [half][n][c][q]
__device__ float g_pden[2 * 16 * 3072];      // partial denominators [half][n][q]

// ---------------- packed f32x2 helpers ----------------
__device__ __forceinline__ ull pk2(float a, float b) {
    ull r; asm("mov.b64 %0,{%1,%2};" : "=l"(r) : "f"(a), "f"(b)); return r;
}
__device__ __forceinline__ void upk2(float& a, float& b, ull v) {
    asm("mov.b64 {%0,%1},%2;" : "=f"(a), "=f"(b) : "l"(v));
}
__device__ __forceinline__ ull fma2(ull a, ull b, ull c) {
    ull d; asm("fma.rn.f32x2 %0,%1,%2,%3;" : "=l"(d) : "l"(a), "l"(b), "l"(c)); return d;
}
__device__ __forceinline__ ull add2(ull a, ull b) {
    ull d; asm("add.rn.f32x2 %0,%1,%2;" : "=l"(d) : "l"(a), "l"(b)); return d;
}
__device__ __forceinline__ ull mul2(ull a, ull b) {
    ull d; asm("mul.rn.f32x2 %0,%1,%2;" : "=l"(d) : "l"(a), "l"(b)); return d;
}

// ---------------- weight repack ----------------
__global__ void repack_kernel(const float* __restrict__ wq, const float* __restrict__ wk,
                              const float* __restrict__ wv, const float* __restrict__ wo)
{
    int i = blockIdx.x * blockDim.x + threadIdx.x;
    if (i < 3 * 18432) {
        int t = i / 18432, r = i % 18432;
        int pos = r >> 5, co = r & 31;
        const float* w = (t == 0) ? wq : (t == 1) ? wk : wv;
        g_wqkv[i] = w[co * 576 + pos];
    } else if (i < 3 * 18432 + 18432) {
        int r = i - 3 * 18432;
        int pos = r >> 6, co = r & 63;
        g_wo[r] = wo[co * 288 + pos];
    }
}

// ---------------- QKV conv3x3 (64 -> 32), z = t*2 + co-half ----------------
__global__ __launch_bounds__(128) void conv_qkv_kernel(
    const float* __restrict__ x,
    const float* __restrict__ bq, const float* __restrict__ bk, const float* __restrict__ bv)
{
    extern __shared__ float sm[];
    float* sx = sm;               // 64*10*18 = 11520 floats
    float* sw = sm + 11520;       // 576*16   = 9216 floats
    const int t = blockIdx.z >> 1, half = blockIdx.z & 1;
    const int y0 = blockIdx.y * 8, x0 = blockIdx.x * 16;
    const int tid = threadIdx.x;

    for (int idx = tid; idx < 11520; idx += 128) {
        int ci = idx / 180, rem = idx % 180;
        int ry = rem / 18, rx = rem % 18;
        int gy = y0 + ry - 1, gx = x0 + rx - 1;
        float v = 0.f;
        if (gy >= 0 && gy < HH && gx >= 0 && gx < WW) v = x[ci * HW + gy * WW + gx];
        sx[idx] = v;
    }
    {
        const float* wsrc = g_wqkv + t * 18432 + half * 16;
        for (int idx = tid; idx < 2304; idx += 128) {
            int pos = idx >> 2, q = idx & 3;
            float4 w4 = *(const float4*)(wsrc + pos * 32 + q * 4);
            *(float4*)&sw[pos * 16 + q * 4] = w4;
        }
    }
    __syncthreads();

    const int ty = tid >> 4, tx = tid & 15;
    const float* bias = (t == 0) ? bq : (t == 1) ? bk : bv;
    float acc[16];
    #pragma unroll
    for (int c = 0; c < 16; c++) acc[c] = bias[half * 16 + c];

    for (int ci = 0; ci < 64; ci++) {
        #pragma unroll
        for (int ky = 0; ky < 3; ky++) {
            #pragma unroll
            for (int kx = 0; kx < 3; kx++) {
                float xv = sx[(ci * 10 + ty + ky) * 18 + tx + kx];
                const float4* wr = (const float4*)&sw[(ci * 9 + ky * 3 + kx) * 16];
                #pragma unroll
                for (int jj = 0; jj < 4; jj++) {
                    float4 w4 = wr[jj];
                    acc[4*jj+0] = fmaf(xv, w4.x, acc[4*jj+0]);
                    acc[4*jj+1] = fmaf(xv, w4.y, acc[4*jj+1]);
                    acc[4*jj+2] = fmaf(xv, w4.z, acc[4*jj+2]);
                    acc[4*jj+3] = fmaf(xv, w4.w, acc[4*jj+3]);
                }
            }
        }
    }
    const int y = y0 + ty, xx = x0 + tx;
    if (t == 0) {
        #pragma unroll
        for (int c = 0; c < 16; c++)
            g_qs[(half * 16 + c) * HW + y * WW + xx] = acc[c] * LOG2E_HALF;
    } else {
        float* dst = (t == 1) ? g_kp : g_vp;
        #pragma unroll
        for (int c = 0; c < 16; c++)
            dst[((half * 16 + c) * 144 + y + 8) * 64 + (xx + 8)] = acc[c];
    }
}

// ---------------- block-local attention, split-KV over blockIdx.z -------------------
// grid (8 q-chunks, 16 blocks, 2 kv-halves); 192 threads x 2 queries.
// smem: component-sliced half-K/V: 8 * 2880 floats = 92160 bytes -> 2 CTAs/SM.
__global__ __launch_bounds__(192) void attn_kernel()
{
    extern __shared__ float sk[];
    const int n = blockIdx.y;
    const int half = blockIdx.z;
    const int h = n >> 1, j = n & 1;
    const int tid = threadIdx.x;

    // Stage half of the flanged K/V (exact as_strided flat map):
    // flat = h*24576 + d*6144 + (half*72 + row)*48 + j*24 + m1
    {
        const int kbase = h * 24576 + j * 24 + half * 72 * 48;
        for (int it = tid; it < MLEN; it += 192) {            // 4 comps * 72 rows * 10 vec4
            int c = it / 720, rem = it % 720;
            int row = rem / 10, v4 = rem % 10;
            int m = row * 40 + v4 * 4;
            int g = kbase + c * 6144 + row * 48 + v4 * 4;
            *(float4*)&sk[c * MLEN + m]         = *(const float4*)&g_kp[g];
            *(float4*)&sk[4*MLEN + c * MLEN + m] = *(const float4*)&g_vp[g];
        }
    }
    __syncthreads();

    const int qA = blockIdx.x * 384 + tid;
    const int qB = qA + 192;
    const int yA = qA / 24, xA = qA - yA * 24;
    const int yB = qB / 24, xB = qB - yB * 24;
    const int aA = yA * WW + j * 24 + xA;
    const int aB = yB * WW + j * 24 + xB;
    const int cb = h * 4 * HW;

    const ull qa0 = pk2(g_qs[cb + aA],        g_qs[cb + aA]);
    const ull qa1 = pk2(g_qs[cb + HW + aA],   g_qs[cb + HW + aA]);
    const ull qa2 = pk2(g_qs[cb + 2*HW + aA], g_qs[cb + 2*HW + aA]);
    const ull qa3 = pk2(g_qs[cb + 3*HW + aA], g_qs[cb + 3*HW + aA]);
    const ull qb0 = pk2(g_qs[cb + aB],        g_qs[cb + aB]);
    const ull qb1 = pk2(g_qs[cb + HW + aB],   g_qs[cb + HW + aB]);
    const ull qb2 = pk2(g_qs[cb + 2*HW + aB], g_qs[cb + 2*HW + aB]);
    const ull qb3 = pk2(g_qs[cb + 3*HW + aB], g_qs[cb + 3*HW + aB]);

    const ull MAG2 = pk2(12582912.0f, 12582912.0f);
    const ull NEG1 = pk2(-1.0f, -1.0f);
    const ull C4 = pk2(9.6679604887e-3f, 9.6679604887e-3f);   // deg-4 tuned
    const ull C3 = pk2(5.5503785733e-2f, 5.5503785733e-2f);
    const ull C2 = pk2(2.4022597616e-1f, 2.4022597616e-1f);
    const ull C1 = pk2(6.9314719846e-1f, 6.9314719846e-1f);
    const ull ONE2 = pk2(1.0f, 1.0f);

    ull denA = 0, aAx = 0, aAy = 0, aAz = 0, aAw = 0;
    ull denB = 0, aBx = 0, aBy = 0, aBz = 0, aBw = 0;

    auto qstep = [&](ull q0, ull q1, ull q2, ull q3,
                     ull kx, ull ky, ull kz, ull kw,
                     ull vx, ull vy, ull vz, ull vw,
                     ull& den, ull& ax, ull& ay, ull& az, ull& aw)
    {
        ull s2 = fma2(q3, kw, fma2(q2, kz, fma2(q1, ky, mul2(q0, kx))));
        ull r2 = add2(s2, MAG2);
        ull t2 = fma2(r2, NEG1, MAG2);        // C - r
        ull f2 = add2(s2, t2);                // f = s - (r - C)
        ull p2 = fma2(C4, f2, C3);
        p2 = fma2(p2, f2, C2);
        p2 = fma2(p2, f2, C1);
        p2 = fma2(p2, f2, ONE2);
        float pl, ph, rl, rh;
        upk2(pl, ph, p2); upk2(rl, rh, r2);
        int el = __float_as_int(pl) + (__float_as_int(rl) << 23);
        int eh = __float_as_int(ph) + (__float_as_int(rh) << 23);
        ull e2 = pk2(__int_as_float(el), __int_as_float(eh));
        den = add2(den, e2);
        ax = fma2(e2, vx, ax); ay = fma2(e2, vy, ay);
        az = fma2(e2, vz, az); aw = fma2(e2, vw, aw);
    };

    const float* skx = sk;
    const float* sky = sk + MLEN;
    const float* skz = sk + 2*MLEN;
    const float* skw = sk + 3*MLEN;
    const float* svx = sk + 4*MLEN;
    const float* svy = sk + 5*MLEN;
    const float* svz = sk + 6*MLEN;
    const float* svw = sk + 7*MLEN;

    for (int m = 0; m < MLEN; m += 4) {
        ulonglong2 kx = *(const ulonglong2*)(skx + m);
        ulonglong2 ky = *(const ulonglong2*)(sky + m);
        ulonglong2 kz = *(const ulonglong2*)(skz + m);
        ulonglong2 kw = *(const ulonglong2*)(skw + m);
        ulonglong2 vx = *(const ulonglong2*)(svx + m);
        ulonglong2 vy = *(const ulonglong2*)(svy + m);
        ulonglong2 vz = *(const ulonglong2*)(svz + m);
        ulonglong2 vw = *(const ulonglong2*)(svw + m);
        qstep(qa0,qa1,qa2,qa3, kx.x,ky.x,kz.x,kw.x, vx.x,vy.x,vz.x,vw.x, denA,aAx,aAy,aAz,aAw);
        qstep(qa0,qa1,qa2,qa3, kx.y,ky.y,kz.y,kw.y, vx.y,vy.y,vz.y,vw.y, denA,aAx,aAy,aAz,aAw);
        qstep(qb0,qb1,qb2,qb3, kx.x,ky.x,kz.x,kw.x, vx.x,vy.x,vz.x,vw.x, denB,aBx,aBy,aBz,aBw);
        qstep(qb0,qb1,qb2,qb3, kx.y,ky.y,kz.y,kw.y, vx.y,vy.y,vz.y,vw.y, denB,aBx,aBy,aBz,aBw);
    }

    // partial outputs: sum the two packed halves, store num x4 + den per query
    float lo, hi;
    const int pbase = (half * 16 + n) * 4 * 3072;
    const int dbase = (half * 16 + n) * 3072;
    upk2(lo, hi, denA); g_pden[dbase + qA] = lo + hi;
    upk2(lo, hi, denB); g_pden[dbase + qB] = lo + hi;
    upk2(lo, hi, aAx); g_pnum[pbase + qA]          = lo + hi;
    upk2(lo, hi, aAy); g_pnum[pbase + 3072 + qA]   = lo + hi;
    upk2(lo, hi, aAz); g_pnum[pbase + 6144 + qA]   = lo + hi;
    upk2(lo, hi, aAw); g_pnum[pbase + 9216 + qA]   = lo + hi;
    upk2(lo, hi, aBx); g_pnum[pbase + qB]          = lo + hi;
    upk2(lo, hi, aBy); g_pnum[pbase + 3072 + qB]   = lo + hi;
    upk2(lo, hi, aBz); g_pnum[pbase + 6144 + qB]   = lo + hi;
    upk2(lo, hi, aBw); g_pnum[pbase + 9216 + qB]   = lo + hi;
}

// ---------------- combine split-KV partials into g_o ----------------
__global__ __launch_bounds__(256) void combine_kernel()
{
    int idx = blockIdx.x * 256 + threadIdx.x;      // 16*3072 = 49152
    int n = idx / 3072, q = idx - n * 3072;
    int h = n >> 1, j = n & 1;
    int y = q / 24, x = q - y * 24;
    int a = y * WW + j * 24 + x;
    int cb = h * 4 * HW;
    int d0 = n * 3072 + q, d1 = (16 + n) * 3072 + q;
    float den = g_pden[d0] + g_pden[d1];
    float r = 1.0f / den;
    int p0 = n * 4 * 3072 + q, p1 = (16 + n) * 4 * 3072 + q;
    #pragma unroll
    for (int c = 0; c < 4; c++)
        g_o[cb + c * HW + a] = (g_pnum[p0 + c * 3072] + g_pnum[p1 + c * 3072]) * r;
}

// ---------------- output conv3x3 (32 -> 64), z = co quarter ----------------
__global__ __launch_bounds__(128) void conv_out_kernel(float* __restrict__ out)
{
    extern __shared__ float sm[];
    float* sx = sm;               // 32*10*18 = 5760 floats
    float* sw = sm + 5760;        // 288*16   = 4608 floats
    const int z  = blockIdx.z;
    const int y0 = blockIdx.y * 8, x0 = blockIdx.x * 16;
    const int tid = threadIdx.x;

    for (int idx = tid; idx < 5760; idx += 128) {
        int ci = idx / 180, rem = idx % 180;
        int ry = rem / 18, rx = rem % 18;
        int gy = y0 + ry - 1, gx = x0 + rx - 1;
        float v = 0.f;
        if (gy >= 0 && gy < HH && gx >= 0 && gx < WW) v = g_o[ci * HW + gy * WW + gx];
        sx[idx] = v;
    }
    for (int idx = tid; idx < 1152; idx += 128) {
        int pos = idx >> 2, q = idx & 3;
        float4 w4 = *(const float4*)(g_wo + pos * 64 + z * 16 + q * 4);
        *(float4*)&sw[pos * 16 + q * 4] = w4;
    }
    __syncthreads();

    const int ty = tid >> 4, tx = tid & 15;
    float acc[16];
    #pragma unroll
    for (int c = 0; c < 16; c++) acc[c] = 0.f;

    for (int ci = 0; ci < 32; ci++) {
        #pragma unroll
        for (int ky = 0; ky < 3; ky++) {
            #pragma unroll
            for (int kx = 0; kx < 3; kx++) {
                float xv = sx[(ci * 10 + ty + ky) * 18 + tx + kx];
                const float4* wr = (const float4*)&sw[(ci * 9 + ky * 3 + kx) * 16];
                #pragma unroll
                for (int jj = 0; jj < 4; jj++) {
                    float4 w4 = wr[jj];
                    acc[4*jj+0] = fmaf(xv, w4.x, acc[4*jj+0]);
                    acc[4*jj+1] = fmaf(xv, w4.y, acc[4*jj+1]);
                    acc[4*jj+2] = fmaf(xv, w4.z, acc[4*jj+2]);
                    acc[4*jj+3] = fmaf(xv, w4.w, acc[4*jj+3]);
                }
            }
        }
    }
    const int y = y0 + ty, xx = x0 + tx;
    #pragma unroll
    for (int c = 0; c < 16; c++)
        out[(z * 16 + c) * HW + y * WW + xx] = acc[c];
}

// ---------------- launch ----------------
extern "C" void kernel_launch(void* const* d_in, const int* in_sizes, int n_in,
                              void* d_out, int out_size)
{
    const float* x  = (const float*)d_in[0];
    const float* wq = (const float*)d_in[1];
    const float* bq = (const float*)d_in[2];
    const float* wk = (const float*)d_in[3];
    const float* bk = (const float*)d_in[4];
    const float* wv = (const float*)d_in[5];
    const float* bv = (const float*)d_in[6];
    const float* wo = (const float*)d_in[7];
    float* out = (float*)d_out;

    cudaFuncSetAttribute(conv_qkv_kernel, cudaFuncAttributeMaxDynamicSharedMemorySize, 82944);
    cudaFuncSetAttribute(attn_kernel,     cudaFuncAttributeMaxDynamicSharedMemorySize, 92160);
    cudaFuncSetAttribute(conv_out_kernel, cudaFuncAttributeMaxDynamicSharedMemorySize, 41472);

    repack_kernel<<<(73728 + 255) / 256, 256>>>(wq, wk, wv, wo);
    conv_qkv_kernel<<<dim3(3, 16, 6), 128, 82944>>>(x, bq, bk, bv);
    attn_kernel<<<dim3(8, 16, 2), 192, 92160>>>();
    combine_kernel<<<192, 256>>>();
    conv_out_kernel<<<dim3(3, 16, 4), 128, 41472>>>(out);
}

// round 5
// speedup vs baseline: 1.3983x; 1.0080x over previous
#include <cuda_runtime.h>

#define HH 128
#define WW 48
#define HW 6144            // 128*48
#define NSPLIT 3
#define MLEN 1920          // 5760 / 3 (split-KV)
#define LOG2E_HALF 0.72134752044448170f   // 0.5*log2(e)

typedef unsigned long long ull;

// ---------------- scratch (device globals) ----------------
__device__ float g_qs[32 * HW];          // q conv output, pre-scaled
__device__ float g_kp[32 * 144 * 64];    // flange-padded k (flat, pad stays 0)
__device__ float g_vp[32 * 144 * 64];    // flange-padded v
__device__ float g_o [32 * HW];          // attention output
__device__ float g_wqkv[3 * 576 * 32];   // repacked [t][pos][co]
__device__ float g_wo[288 * 64];         // repacked [pos][co]
__device__ float g_pnum[NSPLIT * 16 * 4 * 3072];  // partial numerators [s][n][c][q]
__device__ float g_pden[NSPLIT * 16 * 3072];      // partial denominators [s][n][q]

// ---------------- packed f32x2 helpers ----------------
__device__ __forceinline__ ull pk2(float a, float b) {
    ull r; asm("mov.b64 %0,{%1,%2};" : "=l"(r) : "f"(a), "f"(b)); return r;
}
__device__ __forceinline__ void upk2(float& a, float& b, ull v) {
    asm("mov.b64 {%0,%1},%2;" : "=f"(a), "=f"(b) : "l"(v));
}
__device__ __forceinline__ ull fma2(ull a, ull b, ull c) {
    ull d; asm("fma.rn.f32x2 %0,%1,%2,%3;" : "=l"(d) : "l"(a), "l"(b), "l"(c)); return d;
}
__device__ __forceinline__ ull add2(ull a, ull b) {
    ull d; asm("add.rn.f32x2 %0,%1,%2;" : "=l"(d) : "l"(a), "l"(b)); return d;
}
__device__ __forceinline__ ull mul2(ull a, ull b) {
    ull d; asm("mul.rn.f32x2 %0,%1,%2;" : "=l"(d) : "l"(a), "l"(b)); return d;
}

// ---------------- weight repack ----------------
__global__ void repack_kernel(const float* __restrict__ wq, const float* __restrict__ wk,
                              const float* __restrict__ wv, const float* __restrict__ wo)
{
    int i = blockIdx.x * blockDim.x + threadIdx.x;
    if (i < 3 * 18432) {
        int t = i / 18432, r = i % 18432;
        int pos = r >> 5, co = r & 31;
        const float* w = (t == 0) ? wq : (t == 1) ? wk : wv;
        g_wqkv[i] = w[co * 576 + pos];
    } else if (i < 3 * 18432 + 18432) {
        int r = i - 3 * 18432;
        int pos = r >> 6, co = r & 63;
        g_wo[r] = wo[co * 288 + pos];
    }
}

// ---------------- QKV conv3x3 (64 -> 32), z = t*2 + co-half, packed f32x2 -----------
__global__ __launch_bounds__(128) void conv_qkv_kernel(
    const float* __restrict__ x,
    const float* __restrict__ bq, const float* __restrict__ bk, const float* __restrict__ bv)
{
    extern __shared__ float sm[];
    float* sx = sm;               // 64*10*18 = 11520 floats
    float* sw = sm + 11520;       // 576*16   = 9216 floats
    const int t = blockIdx.z >> 1, half = blockIdx.z & 1;
    const int y0 = blockIdx.y * 8, x0 = blockIdx.x * 16;
    const int tid = threadIdx.x;

    for (int idx = tid; idx < 11520; idx += 128) {
        int ci = idx / 180, rem = idx % 180;
        int ry = rem / 18, rx = rem % 18;
        int gy = y0 + ry - 1, gx = x0 + rx - 1;
        float v = 0.f;
        if (gy >= 0 && gy < HH && gx >= 0 && gx < WW) v = x[ci * HW + gy * WW + gx];
        sx[idx] = v;
    }
    {
        const float* wsrc = g_wqkv + t * 18432 + half * 16;
        for (int idx = tid; idx < 2304; idx += 128) {
            int pos = idx >> 2, q = idx & 3;
            float4 w4 = *(const float4*)(wsrc + pos * 32 + q * 4);
            *(float4*)&sw[pos * 16 + q * 4] = w4;
        }
    }
    __syncthreads();

    const int ty = tid >> 4, tx = tid & 15;
    const float* bias = (t == 0) ? bq : (t == 1) ? bk : bv;
    ull acc2[8];
    #pragma unroll
    for (int c = 0; c < 8; c++) acc2[c] = pk2(bias[half * 16 + 2*c], bias[half * 16 + 2*c + 1]);

    for (int ci = 0; ci < 64; ci++) {
        #pragma unroll
        for (int ky = 0; ky < 3; ky++) {
            #pragma unroll
            for (int kx = 0; kx < 3; kx++) {
                float xv = sx[(ci * 10 + ty + ky) * 18 + tx + kx];
                ull xv2 = pk2(xv, xv);
                const ulonglong2* wr = (const ulonglong2*)&sw[(ci * 9 + ky * 3 + kx) * 16];
                #pragma unroll
                for (int jj = 0; jj < 4; jj++) {
                    ulonglong2 w = wr[jj];
                    acc2[2*jj]   = fma2(xv2, w.x, acc2[2*jj]);
                    acc2[2*jj+1] = fma2(xv2, w.y, acc2[2*jj+1]);
                }
            }
        }
    }
    const int y = y0 + ty, xx = x0 + tx;
    float av[16];
    #pragma unroll
    for (int c = 0; c < 8; c++) upk2(av[2*c], av[2*c+1], acc2[c]);
    if (t == 0) {
        #pragma unroll
        for (int c = 0; c < 16; c++)
            g_qs[(half * 16 + c) * HW + y * WW + xx] = av[c] * LOG2E_HALF;
    } else {
        float* dst = (t == 1) ? g_kp : g_vp;
        #pragma unroll
        for (int c = 0; c < 16; c++)
            dst[((half * 16 + c) * 144 + y + 8) * 64 + (xx + 8)] = av[c];
    }
}

// ---------------- block-local attention, 3-way split-KV over blockIdx.z -------------
// grid (8 q-chunks, 16 blocks, 3 kv-thirds); 192 threads x 2 queries.
// smem: component-sliced third-K/V: 8 * 1920 floats = 61440 bytes -> 3 CTAs/SM.
__global__ __launch_bounds__(192, 3) void attn_kernel()
{
    extern __shared__ float sk[];
    const int n = blockIdx.y;
    const int s = blockIdx.z;
    const int h = n >> 1, j = n & 1;
    const int tid = threadIdx.x;

    // Stage one third of the flanged K/V (exact as_strided flat map):
    // flat = h*24576 + d*6144 + (s*48 + row)*48 + j*24 + m1
    {
        const int kbase = h * 24576 + j * 24 + s * 2304;
        for (int it = tid; it < MLEN; it += 192) {            // 4 comps * 48 rows * 10 vec4
            int c = it / 480, rem = it % 480;
            int row = rem / 10, v4 = rem % 10;
            int m = row * 40 + v4 * 4;
            int g = kbase + c * 6144 + row * 48 + v4 * 4;
            *(float4*)&sk[c * MLEN + m]          = *(const float4*)&g_kp[g];
            *(float4*)&sk[4*MLEN + c * MLEN + m] = *(const float4*)&g_vp[g];
        }
    }
    __syncthreads();

    const int qA = blockIdx.x * 384 + tid;
    const int qB = qA + 192;
    const int yA = qA / 24, xA = qA - yA * 24;
    const int yB = qB / 24, xB = qB - yB * 24;
    const int aA = yA * WW + j * 24 + xA;
    const int aB = yB * WW + j * 24 + xB;
    const int cb = h * 4 * HW;

    const ull qa0 = pk2(g_qs[cb + aA],        g_qs[cb + aA]);
    const ull qa1 = pk2(g_qs[cb + HW + aA],   g_qs[cb + HW + aA]);
    const ull qa2 = pk2(g_qs[cb + 2*HW + aA], g_qs[cb + 2*HW + aA]);
    const ull qa3 = pk2(g_qs[cb + 3*HW + aA], g_qs[cb + 3*HW + aA]);
    const ull qb0 = pk2(g_qs[cb + aB],        g_qs[cb + aB]);
    const ull qb1 = pk2(g_qs[cb + HW + aB],   g_qs[cb + HW + aB]);
    const ull qb2 = pk2(g_qs[cb + 2*HW + aB], g_qs[cb + 2*HW + aB]);
    const ull qb3 = pk2(g_qs[cb + 3*HW + aB], g_qs[cb + 3*HW + aB]);

    const ull MAG2 = pk2(12582912.0f, 12582912.0f);
    const ull NEG1 = pk2(-1.0f, -1.0f);
    // degree-3 economized exp2 on [-0.5, 0.5] (abs err ~8e-5)
    const ull C3 = pk2(5.59208e-2f, 5.59208e-2f);
    const ull C2 = pk2(2.4263100e-1f, 2.4263100e-1f);
    const ull C1 = pk2(6.9312120e-1f, 6.9312120e-1f);
    const ull C0 = pk2(9.9992486e-1f, 9.9992486e-1f);

    ull denA = 0, aAx = 0, aAy = 0, aAz = 0, aAw = 0;
    ull denB = 0, aBx = 0, aBy = 0, aBz = 0, aBw = 0;

    auto qstep = [&](ull q0, ull q1, ull q2, ull q3,
                     ull kx, ull ky, ull kz, ull kw,
                     ull vx, ull vy, ull vz, ull vw,
                     ull& den, ull& ax, ull& ay, ull& az, ull& aw)
    {
        ull s2 = fma2(q3, kw, fma2(q2, kz, fma2(q1, ky, mul2(q0, kx))));
        ull r2 = add2(s2, MAG2);
        ull t2 = fma2(r2, NEG1, MAG2);        // MAG - r
        ull f2 = add2(s2, t2);                // f = s - (r - MAG)
        ull p2 = fma2(C3, f2, C2);
        p2 = fma2(p2, f2, C1);
        p2 = fma2(p2, f2, C0);
        float pl, ph, rl, rh;
        upk2(pl, ph, p2); upk2(rl, rh, r2);
        int el = __float_as_int(pl) + (__float_as_int(rl) << 23);
        int eh = __float_as_int(ph) + (__float_as_int(rh) << 23);
        ull e2 = pk2(__int_as_float(el), __int_as_float(eh));
        den = add2(den, e2);
        ax = fma2(e2, vx, ax); ay = fma2(e2, vy, ay);
        az = fma2(e2, vz, az); aw = fma2(e2, vw, aw);
    };

    const float* skx = sk;
    const float* sky = sk + MLEN;
    const float* skz = sk + 2*MLEN;
    const float* skw = sk + 3*MLEN;
    const float* svx = sk + 4*MLEN;
    const float* svy = sk + 5*MLEN;
    const float* svz = sk + 6*MLEN;
    const float* svw = sk + 7*MLEN;

    for (int m = 0; m < MLEN; m += 4) {
        ulonglong2 kx = *(const ulonglong2*)(skx + m);
        ulonglong2 ky = *(const ulonglong2*)(sky + m);
        ulonglong2 kz = *(const ulonglong2*)(skz + m);
        ulonglong2 kw = *(const ulonglong2*)(skw + m);
        ulonglong2 vx = *(const ulonglong2*)(svx + m);
        ulonglong2 vy = *(const ulonglong2*)(svy + m);
        ulonglong2 vz = *(const ulonglong2*)(svz + m);
        ulonglong2 vw = *(const ulonglong2*)(svw + m);
        qstep(qa0,qa1,qa2,qa3, kx.x,ky.x,kz.x,kw.x, vx.x,vy.x,vz.x,vw.x, denA,aAx,aAy,aAz,aAw);
        qstep(qa0,qa1,qa2,qa3, kx.y,ky.y,kz.y,kw.y, vx.y,vy.y,vz.y,vw.y, denA,aAx,aAy,aAz,aAw);
        qstep(qb0,qb1,qb2,qb3, kx.x,ky.x,kz.x,kw.x, vx.x,vy.x,vz.x,vw.x, denB,aBx,aBy,aBz,aBw);
        qstep(qb0,qb1,qb2,qb3, kx.y,ky.y,kz.y,kw.y, vx.y,vy.y,vz.y,vw.y, denB,aBx,aBy,aBz,aBw);
    }

    float lo, hi;
    const int pbase = (s * 16 + n) * 4 * 3072;
    const int dbase = (s * 16 + n) * 3072;
    upk2(lo, hi, denA); g_pden[dbase + qA] = lo + hi;
    upk2(lo, hi, denB); g_pden[dbase + qB] = lo + hi;
    upk2(lo, hi, aAx); g_pnum[pbase + qA]          = lo + hi;
    upk2(lo, hi, aAy); g_pnum[pbase + 3072 + qA]   = lo + hi;
    upk2(lo, hi, aAz); g_pnum[pbase + 6144 + qA]   = lo + hi;
    upk2(lo, hi, aAw); g_pnum[pbase + 9216 + qA]   = lo + hi;
    upk2(lo, hi, aBx); g_pnum[pbase + qB]          = lo + hi;
    upk2(lo, hi, aBy); g_pnum[pbase + 3072 + qB]   = lo + hi;
    upk2(lo, hi, aBz); g_pnum[pbase + 6144 + qB]   = lo + hi;
    upk2(lo, hi, aBw); g_pnum[pbase + 9216 + qB]   = lo + hi;
}

// ---------------- combine split-KV partials into g_o (float4 per thread) ------------
__global__ __launch_bounds__(256) void combine_kernel()
{
    int idx = blockIdx.x * 256 + threadIdx.x;      // 16*3072/4 = 12288
    int n = idx / 768, rem = idx - n * 768;
    int q = rem * 4;
    int h = n >> 1, j = n & 1;
    int y = q / 24, x = q - y * 24;
    int a = y * WW + j * 24 + x;
    int cb = h * 4 * HW;

    float4 d0 = *(const float4*)&g_pden[n * 3072 + q];
    float4 d1 = *(const float4*)&g_pden[(16 + n) * 3072 + q];
    float4 d2 = *(const float4*)&g_pden[(32 + n) * 3072 + q];
    float4 r;
    r.x = 1.0f / (d0.x + d1.x + d2.x);
    r.y = 1.0f / (d0.y + d1.y + d2.y);
    r.z = 1.0f / (d0.z + d1.z + d2.z);
    r.w = 1.0f / (d0.w + d1.w + d2.w);

    #pragma unroll
    for (int c = 0; c < 4; c++) {
        float4 p0 = *(const float4*)&g_pnum[(n * 4 + c) * 3072 + q];
        float4 p1 = *(const float4*)&g_pnum[((16 + n) * 4 + c) * 3072 + q];
        float4 p2 = *(const float4*)&g_pnum[((32 + n) * 4 + c) * 3072 + q];
        float4 o;
        o.x = (p0.x + p1.x + p2.x) * r.x;
        o.y = (p0.y + p1.y + p2.y) * r.y;
        o.z = (p0.z + p1.z + p2.z) * r.z;
        o.w = (p0.w + p1.w + p2.w) * r.w;
        *(float4*)&g_o[cb + c * HW + a] = o;
    }
}

// ---------------- output conv3x3 (32 -> 64), z = co quarter, packed f32x2 -----------
__global__ __launch_bounds__(128) void conv_out_kernel(float* __restrict__ out)
{
    extern __shared__ float sm[];
    float* sx = sm;               // 32*10*18 = 5760 floats
    float* sw = sm + 5760;        // 288*16   = 4608 floats
    const int z  = blockIdx.z;
    const int y0 = blockIdx.y * 8, x0 = blockIdx.x * 16;
    const int tid = threadIdx.x;

    for (int idx = tid; idx < 5760; idx += 128) {
        int ci = idx / 180, rem = idx % 180;
        int ry = rem / 18, rx = rem % 18;
        int gy = y0 + ry - 1, gx = x0 + rx - 1;
        float v = 0.f;
        if (gy >= 0 && gy < HH && gx >= 0 && gx < WW) v = g_o[ci * HW + gy * WW + gx];
        sx[idx] = v;
    }
    for (int idx = tid; idx < 1152; idx += 128) {
        int pos = idx >> 2, q = idx & 3;
        float4 w4 = *(const float4*)(g_wo + pos * 64 + z * 16 + q * 4);
        *(float4*)&sw[pos * 16 + q * 4] = w4;
    }
    __syncthreads();

    const int ty = tid >> 4, tx = tid & 15;
    ull acc2[8];
    #pragma unroll
    for (int c = 0; c < 8; c++) acc2[c] = 0;

    for (int ci = 0; ci < 32; ci++) {
        #pragma unroll
        for (int ky = 0; ky < 3; ky++) {
            #pragma unroll
            for (int kx = 0; kx < 3; kx++) {
                float xv = sx[(ci * 10 + ty + ky) * 18 + tx + kx];
                ull xv2 = pk2(xv, xv);
                const ulonglong2* wr = (const ulonglong2*)&sw[(ci * 9 + ky * 3 + kx) * 16];
                #pragma unroll
                for (int jj = 0; jj < 4; jj++) {
                    ulonglong2 w = wr[jj];
                    acc2[2*jj]   = fma2(xv2, w.x, acc2[2*jj]);
                    acc2[2*jj+1] = fma2(xv2, w.y, acc2[2*jj+1]);
                }
            }
        }
    }
    const int y = y0 + ty, xx = x0 + tx;
    float av[16];
    #pragma unroll
    for (int c = 0; c < 8; c++) upk2(av[2*c], av[2*c+1], acc2[c]);
    #pragma unroll
    for (int c = 0; c < 16; c++)
        out[(z * 16 + c) * HW + y * WW + xx] = av[c];
}

// ---------------- launch ----------------
extern "C" void kernel_launch(void* const* d_in, const int* in_sizes, int n_in,
                              void* d_out, int out_size)
{
    const float* x  = (const float*)d_in[0];
    const float* wq = (const float*)d_in[1];
    const float* bq = (const float*)d_in[2];
    const float* wk = (const float*)d_in[3];
    const float* bk = (const float*)d_in[4];
    const float* wv = (const float*)d_in[5];
    const float* bv = (const float*)d_in[6];
    const float* wo = (const float*)d_in[7];
    float* out = (float*)d_out;

    cudaFuncSetAttribute(conv_qkv_kernel, cudaFuncAttributeMaxDynamicSharedMemorySize, 82944);
    cudaFuncSetAttribute(attn_kernel,     cudaFuncAttributeMaxDynamicSharedMemorySize, 61440);
    cudaFuncSetAttribute(conv_out_kernel, cudaFuncAttributeMaxDynamicSharedMemorySize, 41472);

    repack_kernel<<<(73728 + 255) / 256, 256>>>(wq, wk, wv, wo);
    conv_qkv_kernel<<<dim3(3, 16, 6), 128, 82944>>>(x, bq, bk, bv);
    attn_kernel<<<dim3(8, 16, 3), 192, 61440>>>();
    combine_kernel<<<48, 256>>>();
    conv_out_kernel<<<dim3(3, 16, 4), 128, 41472>>>(out);
}

// round 6
// speedup vs baseline: 1.6586x; 1.1861x over previous
#include <cuda_runtime.h>

#define HH 128
#define WW 48
#define HW 6144            // 128*48
#define NSPLIT 3
#define MLEN 1920          // 5760 / 3 (split-KV)
#define LOG2E_HALF 0.72134752044448170f   // 0.5*log2(e)

typedef unsigned long long ull;

// ---------------- scratch (device globals) ----------------
__device__ float g_qs[32 * HW];          // q conv output, pre-scaled
__device__ float g_kp[32 * 144 * 64];    // flange-padded k (flat, pad stays 0)
__device__ float g_vp[32 * 144 * 64];    // flange-padded v
__device__ float g_o [32 * HW];          // attention output
__device__ float g_wqkv[3 * 576 * 32];   // repacked [t][pos][co]
__device__ float g_wo[288 * 64];         // repacked [pos][co]
__device__ float g_pnum[NSPLIT * 16 * 4 * 3072];  // partial numerators [s][n][c][q]
__device__ float g_pden[NSPLIT * 16 * 3072];      // partial denominators [s][n][q]

// ---------------- packed f32x2 helpers ----------------
__device__ __forceinline__ ull pk2(float a, float b) {
    ull r; asm("mov.b64 %0,{%1,%2};" : "=l"(r) : "f"(a), "f"(b)); return r;
}
__device__ __forceinline__ void upk2(float& a, float& b, ull v) {
    asm("mov.b64 {%0,%1},%2;" : "=f"(a), "=f"(b) : "l"(v));
}
__device__ __forceinline__ ull fma2(ull a, ull b, ull c) {
    ull d; asm("fma.rn.f32x2 %0,%1,%2,%3;" : "=l"(d) : "l"(a), "l"(b), "l"(c)); return d;
}
__device__ __forceinline__ ull add2(ull a, ull b) {
    ull d; asm("add.rn.f32x2 %0,%1,%2;" : "=l"(d) : "l"(a), "l"(b)); return d;
}
__device__ __forceinline__ ull mul2(ull a, ull b) {
    ull d; asm("mul.rn.f32x2 %0,%1,%2;" : "=l"(d) : "l"(a), "l"(b)); return d;
}
__device__ __forceinline__ float ex2f(float x) {
    float y; asm("ex2.approx.f32 %0, %1;" : "=f"(y) : "f"(x)); return y;
}

// ---------------- weight repack ----------------
__global__ void repack_kernel(const float* __restrict__ wq, const float* __restrict__ wk,
                              const float* __restrict__ wv, const float* __restrict__ wo)
{
    int i = blockIdx.x * blockDim.x + threadIdx.x;
    if (i < 3 * 18432) {
        int t = i / 18432, r = i % 18432;
        int pos = r >> 5, co = r & 31;
        const float* w = (t == 0) ? wq : (t == 1) ? wk : wv;
        g_wqkv[i] = w[co * 576 + pos];
    } else if (i < 3 * 18432 + 18432) {
        int r = i - 3 * 18432;
        int pos = r >> 6, co = r & 63;
        g_wo[r] = wo[co * 288 + pos];
    }
}

// ---------------- QKV conv3x3 (64 -> 32), z = t*2 + co-half, packed f32x2 -----------
__global__ __launch_bounds__(128) void conv_qkv_kernel(
    const float* __restrict__ x,
    const float* __restrict__ bq, const float* __restrict__ bk, const float* __restrict__ bv)
{
    extern __shared__ float sm[];
    float* sx = sm;               // 64*10*18 = 11520 floats
    float* sw = sm + 11520;       // 576*16   = 9216 floats
    const int t = blockIdx.z >> 1, half = blockIdx.z & 1;
    const int y0 = blockIdx.y * 8, x0 = blockIdx.x * 16;
    const int tid = threadIdx.x;

    for (int idx = tid; idx < 11520; idx += 128) {
        int ci = idx / 180, rem = idx % 180;
        int ry = rem / 18, rx = rem % 18;
        int gy = y0 + ry - 1, gx = x0 + rx - 1;
        float v = 0.f;
        if (gy >= 0 && gy < HH && gx >= 0 && gx < WW) v = x[ci * HW + gy * WW + gx];
        sx[idx] = v;
    }
    {
        const float* wsrc = g_wqkv + t * 18432 + half * 16;
        for (int idx = tid; idx < 2304; idx += 128) {
            int pos = idx >> 2, q = idx & 3;
            float4 w4 = *(const float4*)(wsrc + pos * 32 + q * 4);
            *(float4*)&sw[pos * 16 + q * 4] = w4;
        }
    }
    __syncthreads();

    const int ty = tid >> 4, tx = tid & 15;
    const float* bias = (t == 0) ? bq : (t == 1) ? bk : bv;
    ull acc2[8];
    #pragma unroll
    for (int c = 0; c < 8; c++) acc2[c] = pk2(bias[half * 16 + 2*c], bias[half * 16 + 2*c + 1]);

    for (int ci = 0; ci < 64; ci++) {
        #pragma unroll
        for (int ky = 0; ky < 3; ky++) {
            #pragma unroll
            for (int kx = 0; kx < 3; kx++) {
                float xv = sx[(ci * 10 + ty + ky) * 18 + tx + kx];
                ull xv2 = pk2(xv, xv);
                const ulonglong2* wr = (const ulonglong2*)&sw[(ci * 9 + ky * 3 + kx) * 16];
                #pragma unroll
                for (int jj = 0; jj < 4; jj++) {
                    ulonglong2 w = wr[jj];
                    acc2[2*jj]   = fma2(xv2, w.x, acc2[2*jj]);
                    acc2[2*jj+1] = fma2(xv2, w.y, acc2[2*jj+1]);
                }
            }
        }
    }
    const int y = y0 + ty, xx = x0 + tx;
    float av[16];
    #pragma unroll
    for (int c = 0; c < 8; c++) upk2(av[2*c], av[2*c+1], acc2[c]);
    if (t == 0) {
        #pragma unroll
        for (int c = 0; c < 16; c++)
            g_qs[(half * 16 + c) * HW + y * WW + xx] = av[c] * LOG2E_HALF;
    } else {
        float* dst = (t == 1) ? g_kp : g_vp;
        #pragma unroll
        for (int c = 0; c < 16; c++)
            dst[((half * 16 + c) * 144 + y + 8) * 64 + (xx + 8)] = av[c];
    }
}

// ---------------- block-local attention, 3-way split-KV, MUFU ex2 -------------------
// grid (8 q-chunks, 16 blocks, 3 kv-thirds); 192 threads x 2 queries.
// smem: component-sliced third-K/V: 8 * 1920 floats = 61440 bytes -> 3 CTAs/SM.
__global__ __launch_bounds__(192, 3) void attn_kernel()
{
    extern __shared__ float sk[];
    const int n = blockIdx.y;
    const int s = blockIdx.z;
    const int h = n >> 1, j = n & 1;
    const int tid = threadIdx.x;

    // Stage one third of the flanged K/V (exact as_strided flat map):
    // flat = h*24576 + d*6144 + (s*48 + row)*48 + j*24 + m1
    {
        const int kbase = h * 24576 + j * 24 + s * 2304;
        for (int it = tid; it < MLEN; it += 192) {            // 4 comps * 48 rows * 10 vec4
            int c = it / 480, rem = it % 480;
            int row = rem / 10, v4 = rem % 10;
            int m = row * 40 + v4 * 4;
            int g = kbase + c * 6144 + row * 48 + v4 * 4;
            *(float4*)&sk[c * MLEN + m]          = *(const float4*)&g_kp[g];
            *(float4*)&sk[4*MLEN + c * MLEN + m] = *(const float4*)&g_vp[g];
        }
    }
    __syncthreads();

    const int qA = blockIdx.x * 384 + tid;
    const int qB = qA + 192;
    const int yA = qA / 24, xA = qA - yA * 24;
    const int yB = qB / 24, xB = qB - yB * 24;
    const int aA = yA * WW + j * 24 + xA;
    const int aB = yB * WW + j * 24 + xB;
    const int cb = h * 4 * HW;

    const ull qa0 = pk2(g_qs[cb + aA],        g_qs[cb + aA]);
    const ull qa1 = pk2(g_qs[cb + HW + aA],   g_qs[cb + HW + aA]);
    const ull qa2 = pk2(g_qs[cb + 2*HW + aA], g_qs[cb + 2*HW + aA]);
    const ull qa3 = pk2(g_qs[cb + 3*HW + aA], g_qs[cb + 3*HW + aA]);
    const ull qb0 = pk2(g_qs[cb + aB],        g_qs[cb + aB]);
    const ull qb1 = pk2(g_qs[cb + HW + aB],   g_qs[cb + HW + aB]);
    const ull qb2 = pk2(g_qs[cb + 2*HW + aB], g_qs[cb + 2*HW + aB]);
    const ull qb3 = pk2(g_qs[cb + 3*HW + aB], g_qs[cb + 3*HW + aB]);

    ull denA = 0, aAx = 0, aAy = 0, aAz = 0, aAw = 0;
    ull denB = 0, aBx = 0, aBy = 0, aBz = 0, aBw = 0;

    // 9 FFMA2 on the FMA pipe + 2 ex2 on MUFU per qstep (2 kv elements, 1 query)
    auto qstep = [&](ull q0, ull q1, ull q2, ull q3,
                     ull kx, ull ky, ull kz, ull kw,
                     ull vx, ull vy, ull vz, ull vw,
                     ull& den, ull& ax, ull& ay, ull& az, ull& aw)
    {
        ull s2 = fma2(q3, kw, fma2(q2, kz, fma2(q1, ky, mul2(q0, kx))));
        float sl, sh;
        upk2(sl, sh, s2);                 // free (register-pair aliasing)
        float el = ex2f(sl);              // MUFU
        float eh = ex2f(sh);              // MUFU
        ull e2 = pk2(el, eh);             // free
        den = add2(den, e2);
        ax = fma2(e2, vx, ax); ay = fma2(e2, vy, ay);
        az = fma2(e2, vz, az); aw = fma2(e2, vw, aw);
    };

    const float* skx = sk;
    const float* sky = sk + MLEN;
    const float* skz = sk + 2*MLEN;
    const float* skw = sk + 3*MLEN;
    const float* svx = sk + 4*MLEN;
    const float* svy = sk + 5*MLEN;
    const float* svz = sk + 6*MLEN;
    const float* svw = sk + 7*MLEN;

    for (int m = 0; m < MLEN; m += 4) {
        ulonglong2 kx = *(const ulonglong2*)(skx + m);
        ulonglong2 ky = *(const ulonglong2*)(sky + m);
        ulonglong2 kz = *(const ulonglong2*)(skz + m);
        ulonglong2 kw = *(const ulonglong2*)(skw + m);
        ulonglong2 vx = *(const ulonglong2*)(svx + m);
        ulonglong2 vy = *(const ulonglong2*)(svy + m);
        ulonglong2 vz = *(const ulonglong2*)(svz + m);
        ulonglong2 vw = *(const ulonglong2*)(svw + m);
        qstep(qa0,qa1,qa2,qa3, kx.x,ky.x,kz.x,kw.x, vx.x,vy.x,vz.x,vw.x, denA,aAx,aAy,aAz,aAw);
        qstep(qa0,qa1,qa2,qa3, kx.y,ky.y,kz.y,kw.y, vx.y,vy.y,vz.y,vw.y, denA,aAx,aAy,aAz,aAw);
        qstep(qb0,qb1,qb2,qb3, kx.x,ky.x,kz.x,kw.x, vx.x,vy.x,vz.x,vw.x, denB,aBx,aBy,aBz,aBw);
        qstep(qb0,qb1,qb2,qb3, kx.y,ky.y,kz.y,kw.y, vx.y,vy.y,vz.y,vw.y, denB,aBx,aBy,aBz,aBw);
    }

    float lo, hi;
    const int pbase = (s * 16 + n) * 4 * 3072;
    const int dbase = (s * 16 + n) * 3072;
    upk2(lo, hi, denA); g_pden[dbase + qA] = lo + hi;
    upk2(lo, hi, denB); g_pden[dbase + qB] = lo + hi;
    upk2(lo, hi, aAx); g_pnum[pbase + qA]          = lo + hi;
    upk2(lo, hi, aAy); g_pnum[pbase + 3072 + qA]   = lo + hi;
    upk2(lo, hi, aAz); g_pnum[pbase + 6144 + qA]   = lo + hi;
    upk2(lo, hi, aAw); g_pnum[pbase + 9216 + qA]   = lo + hi;
    upk2(lo, hi, aBx); g_pnum[pbase + qB]          = lo + hi;
    upk2(lo, hi, aBy); g_pnum[pbase + 3072 + qB]   = lo + hi;
    upk2(lo, hi, aBz); g_pnum[pbase + 6144 + qB]   = lo + hi;
    upk2(lo, hi, aBw); g_pnum[pbase + 9216 + qB]   = lo + hi;
}

// ---------------- combine split-KV partials into g_o (float4 per thread) ------------
__global__ __launch_bounds__(256) void combine_kernel()
{
    int idx = blockIdx.x * 256 + threadIdx.x;      // 16*3072/4 = 12288
    int n = idx / 768, rem = idx - n * 768;
    int q = rem * 4;
    int h = n >> 1, j = n & 1;
    int y = q / 24, x = q - y * 24;
    int a = y * WW + j * 24 + x;
    int cb = h * 4 * HW;

    float4 d0 = *(const float4*)&g_pden[n * 3072 + q];
    float4 d1 = *(const float4*)&g_pden[(16 + n) * 3072 + q];
    float4 d2 = *(const float4*)&g_pden[(32 + n) * 3072 + q];
    float4 r;
    r.x = 1.0f / (d0.x + d1.x + d2.x);
    r.y = 1.0f / (d0.y + d1.y + d2.y);
    r.z = 1.0f / (d0.z + d1.z + d2.z);
    r.w = 1.0f / (d0.w + d1.w + d2.w);

    #pragma unroll
    for (int c = 0; c < 4; c++) {
        float4 p0 = *(const float4*)&g_pnum[(n * 4 + c) * 3072 + q];
        float4 p1 = *(const float4*)&g_pnum[((16 + n) * 4 + c) * 3072 + q];
        float4 p2 = *(const float4*)&g_pnum[((32 + n) * 4 + c) * 3072 + q];
        float4 o;
        o.x = (p0.x + p1.x + p2.x) * r.x;
        o.y = (p0.y + p1.y + p2.y) * r.y;
        o.z = (p0.z + p1.z + p2.z) * r.z;
        o.w = (p0.w + p1.w + p2.w) * r.w;
        *(float4*)&g_o[cb + c * HW + a] = o;
    }
}

// ---------------- output conv3x3 (32 -> 64), z = co quarter, packed f32x2 -----------
__global__ __launch_bounds__(128) void conv_out_kernel(float* __restrict__ out)
{
    extern __shared__ float sm[];
    float* sx = sm;               // 32*10*18 = 5760 floats
    float* sw = sm + 5760;        // 288*16   = 4608 floats
    const int z  = blockIdx.z;
    const int y0 = blockIdx.y * 8, x0 = blockIdx.x * 16;
    const int tid = threadIdx.x;

    for (int idx = tid; idx < 5760; idx += 128) {
        int ci = idx / 180, rem = idx % 180;
        int ry = rem / 18, rx = rem % 18;
        int gy = y0 + ry - 1, gx = x0 + rx - 1;
        float v = 0.f;
        if (gy >= 0 && gy < HH && gx >= 0 && gx < WW) v = g_o[ci * HW + gy * WW + gx];
        sx[idx] = v;
    }
    for (int idx = tid; idx < 1152; idx += 128) {
        int pos = idx >> 2, q = idx & 3;
        float4 w4 = *(const float4*)(g_wo + pos * 64 + z * 16 + q * 4);
        *(float4*)&sw[pos * 16 + q * 4] = w4;
    }
    __syncthreads();

    const int ty = tid >> 4, tx = tid & 15;
    ull acc2[8];
    #pragma unroll
    for (int c = 0; c < 8; c++) acc2[c] = 0;

    for (int ci = 0; ci < 32; ci++) {
        #pragma unroll
        for (int ky = 0; ky < 3; ky++) {
            #pragma unroll
            for (int kx = 0; kx < 3; kx++) {
                float xv = sx[(ci * 10 + ty + ky) * 18 + tx + kx];
                ull xv2 = pk2(xv, xv);
                const ulonglong2* wr = (const ulonglong2*)&sw[(ci * 9 + ky * 3 + kx) * 16];
                #pragma unroll
                for (int jj = 0; jj < 4; jj++) {
                    ulonglong2 w = wr[jj];
                    acc2[2*jj]   = fma2(xv2, w.x, acc2[2*jj]);
                    acc2[2*jj+1] = fma2(xv2, w.y, acc2[2*jj+1]);
                }
            }
        }
    }
    const int y = y0 + ty, xx = x0 + tx;
    float av[16];
    #pragma unroll
    for (int c = 0; c < 8; c++) upk2(av[2*c], av[2*c+1], acc2[c]);
    #pragma unroll
    for (int c = 0; c < 16; c++)
        out[(z * 16 + c) * HW + y * WW + xx] = av[c];
}

// ---------------- launch ----------------
extern "C" void kernel_launch(void* const* d_in, const int* in_sizes, int n_in,
                              void* d_out, int out_size)
{
    const float* x  = (const float*)d_in[0];
    const float* wq = (const float*)d_in[1];
    const float* bq = (const float*)d_in[2];
    const float* wk = (const float*)d_in[3];
    const float* bk = (const float*)d_in[4];
    const float* wv = (const float*)d_in[5];
    const float* bv = (const float*)d_in[6];
    const float* wo = (const float*)d_in[7];
    float* out = (float*)d_out;

    cudaFuncSetAttribute(conv_qkv_kernel, cudaFuncAttributeMaxDynamicSharedMemorySize, 82944);
    cudaFuncSetAttribute(attn_kernel,     cudaFuncAttributeMaxDynamicSharedMemorySize, 61440);
    cudaFuncSetAttribute(conv_out_kernel, cudaFuncAttributeMaxDynamicSharedMemorySize, 41472);

    repack_kernel<<<(73728 + 255) / 256, 256>>>(wq, wk, wv, wo);
    conv_qkv_kernel<<<dim3(3, 16, 6), 128, 82944>>>(x, bq, bk, bv);
    attn_kernel<<<dim3(8, 16, 3), 192, 61440>>>();
    combine_kernel<<<48, 256>>>();
    conv_out_kernel<<<dim3(3, 16, 4), 128, 41472>>>(out);
}